// round 5
// baseline (speedup 1.0000x reference)
#include <cuda_runtime.h>
#include <math.h>

#define LSEQ 512
#define BATCH 2
#define DG 256
#define DB 128
#define NH 8
#define HD 32
#define BH (BATCH*NH)   // 16

// ---------------- scratch (device globals; no allocation allowed) ----------------
__device__ float g_xn[BATCH*LSEQ*DG];        // LN(x)                [1024][256]
__device__ float g_q[BH*LSEQ*HD];            // [b*h][l][32]
__device__ float g_k[BH*LSEQ*HD];            // pre-scaled by 1/sqrt(32)
__device__ float g_v[BH*LSEQ*HD];
__device__ float g_gate[BATCH*LSEQ*DG];      // sigmoid(xn@Wg+bg)    [1024][256]
__device__ float g_pb[(size_t)BH*LSEQ*LSEQ]; // pair bias            [b*h][q][k]
__device__ float g_hid[BATCH*LSEQ*DG];       // gate * attn_out      [1024][256]
__device__ float g_wgt[NH*DB];               // b_gamma[i]*Wb[i][h]  [h][i]
__device__ float g_cw[NH];                   // sum_i b_gamma[i]*Wb[i][h]
__device__ float g_bb[NH];                   // b_beta @ Wb[:,h]

// packed f32x2 helpers (sm_10x FFMA2 path — PTX only)
__device__ __forceinline__ void ffma2(unsigned long long& acc,
                                      unsigned long long a,
                                      unsigned long long b) {
    asm("fma.rn.f32x2 %0, %1, %2, %0;" : "+l"(acc) : "l"(a), "l"(b));
}
__device__ __forceinline__ void fadd2(unsigned long long& acc, unsigned long long a) {
    asm("add.rn.f32x2 %0, %1, %0;" : "+l"(acc) : "l"(a));
}
__device__ __forceinline__ float2 unpack2(unsigned long long v) {
    float2 r;
    asm("mov.b64 {%0, %1}, %2;" : "=f"(r.x), "=f"(r.y) : "l"(v));
    return r;
}
// streaming 16B load as two u64 (no L1 persistence wanted)
__device__ __forceinline__ void ldcs2(const void* p, unsigned long long& a,
                                      unsigned long long& b) {
    asm("ld.global.cs.v2.u64 {%0,%1}, [%2];" : "=l"(a), "=l"(b) : "l"(p));
}

// ---------------- prep: fold b_gamma/b_beta into Wb ----------------
__global__ void prep_wb(const float* __restrict__ b_gamma,
                        const float* __restrict__ b_beta,
                        const float* __restrict__ Wb) {
    __shared__ float sc[NH][DB];
    __shared__ float sb[NH][DB];
    int i = threadIdx.x;            // 128 threads
    float g = b_gamma[i];
    float bt = b_beta[i];
#pragma unroll
    for (int h = 0; h < NH; h++) {
        float w = Wb[i*NH + h];
        g_wgt[h*DB + i] = g * w;
        sc[h][i] = g * w;
        sb[h][i] = bt * w;
    }
    __syncthreads();
    if (i < NH) {
        float a = 0.f, b2 = 0.f;
        for (int j = 0; j < DB; j++) { a += sc[i][j]; b2 += sb[i][j]; }
        g_cw[i] = a;
        g_bb[i] = b2;
    }
}

// ---------------- LN over x rows (dim 256), warp per row ----------------
__global__ void __launch_bounds__(128) ln_x(const float* __restrict__ x,
                                            const float* __restrict__ gamma,
                                            const float* __restrict__ beta) {
    int warp = threadIdx.x >> 5, lane = threadIdx.x & 31;
    int row = blockIdx.x * 4 + warp;           // 1024 rows, grid 256
    const float* rp = x + (size_t)row * DG;
    float4 v0 = *(const float4*)(rp + lane*4);
    float4 v1 = *(const float4*)(rp + 128 + lane*4);
    float s1 = v0.x+v0.y+v0.z+v0.w + v1.x+v1.y+v1.z+v1.w;
    float s2 = v0.x*v0.x+v0.y*v0.y+v0.z*v0.z+v0.w*v0.w
             + v1.x*v1.x+v1.y*v1.y+v1.z*v1.z+v1.w*v1.w;
#pragma unroll
    for (int off = 16; off; off >>= 1) {
        s1 += __shfl_xor_sync(0xffffffffu, s1, off);
        s2 += __shfl_xor_sync(0xffffffffu, s2, off);
    }
    float mu = s1 * (1.f/256.f);
    float var = s2 * (1.f/256.f) - mu*mu;
    float rstd = rsqrtf(var + 1e-5f);
    float4 gm0 = *(const float4*)(gamma + lane*4);
    float4 gm1 = *(const float4*)(gamma + 128 + lane*4);
    float4 bt0 = *(const float4*)(beta + lane*4);
    float4 bt1 = *(const float4*)(beta + 128 + lane*4);
    float4 o0, o1;
    o0.x = (v0.x-mu)*rstd*gm0.x + bt0.x; o0.y = (v0.y-mu)*rstd*gm0.y + bt0.y;
    o0.z = (v0.z-mu)*rstd*gm0.z + bt0.z; o0.w = (v0.w-mu)*rstd*gm0.w + bt0.w;
    o1.x = (v1.x-mu)*rstd*gm1.x + bt1.x; o1.y = (v1.y-mu)*rstd*gm1.y + bt1.y;
    o1.z = (v1.z-mu)*rstd*gm1.z + bt1.z; o1.w = (v1.w-mu)*rstd*gm1.w + bt1.w;
    *(float4*)(g_xn + (size_t)row*DG + lane*4) = o0;
    *(float4*)(g_xn + (size_t)row*DG + 128 + lane*4) = o1;
}

// ---------------- fused GEMM: xn @ [Wq|Wk|Wv|Wg] (M=1024, N=1024, K=256) ----------------
__global__ void __launch_bounds__(256) gemm_qkvg(const float* __restrict__ Wq,
                                                 const float* __restrict__ Wk,
                                                 const float* __restrict__ Wv,
                                                 const float* __restrict__ Wg,
                                                 const float* __restrict__ bg) {
    __shared__ __align__(16) float Ast[16*68];   // [k][m] transposed, padded
    __shared__ __align__(16) float Bs [16*68];   // [k][n], padded
    int tid = threadIdx.x;
    int bm = blockIdx.y * 64;
    int bn_g = blockIdx.x * 64;          // 0..1023
    int which = bn_g >> 8;               // 0:Q 1:K 2:V 3:G
    int bn = bn_g & 255;
    const float* W = (which==0) ? Wq : (which==1) ? Wk : (which==2) ? Wv : Wg;
    int ty = tid >> 4, tx = tid & 15;
    int ar = tid >> 2, ac4 = tid & 3;
    int br = tid >> 4, bc4 = tid & 15;
    float acc[4][4] = {};
    for (int kb = 0; kb < 256; kb += 16) {
        float4 av = *(const float4*)(g_xn + (size_t)(bm+ar)*256 + kb + ac4*4);
        Ast[(ac4*4+0)*68 + ar] = av.x;
        Ast[(ac4*4+1)*68 + ar] = av.y;
        Ast[(ac4*4+2)*68 + ar] = av.z;
        Ast[(ac4*4+3)*68 + ar] = av.w;
        *(float4*)&Bs[br*68 + bc4*4] = *(const float4*)(W + (size_t)(kb+br)*256 + bn + bc4*4);
        __syncthreads();
#pragma unroll
        for (int k = 0; k < 16; k++) {
            float4 a = *(float4*)&Ast[k*68 + ty*4];
            float4 b = *(float4*)&Bs [k*68 + tx*4];
            acc[0][0]=fmaf(a.x,b.x,acc[0][0]); acc[0][1]=fmaf(a.x,b.y,acc[0][1]);
            acc[0][2]=fmaf(a.x,b.z,acc[0][2]); acc[0][3]=fmaf(a.x,b.w,acc[0][3]);
            acc[1][0]=fmaf(a.y,b.x,acc[1][0]); acc[1][1]=fmaf(a.y,b.y,acc[1][1]);
            acc[1][2]=fmaf(a.y,b.z,acc[1][2]); acc[1][3]=fmaf(a.y,b.w,acc[1][3]);
            acc[2][0]=fmaf(a.z,b.x,acc[2][0]); acc[2][1]=fmaf(a.z,b.y,acc[2][1]);
            acc[2][2]=fmaf(a.z,b.z,acc[2][2]); acc[2][3]=fmaf(a.z,b.w,acc[2][3]);
            acc[3][0]=fmaf(a.w,b.x,acc[3][0]); acc[3][1]=fmaf(a.w,b.y,acc[3][1]);
            acc[3][2]=fmaf(a.w,b.z,acc[3][2]); acc[3][3]=fmaf(a.w,b.w,acc[3][3]);
        }
        __syncthreads();
    }
    const float kscale = 0.17677669529663687f; // 1/sqrt(32)
#pragma unroll
    for (int i = 0; i < 4; i++) {
#pragma unroll
        for (int j = 0; j < 4; j++) {
            int m = bm + ty*4 + i;
            int n = bn + tx*4 + j;
            float v = acc[i][j];
            if (which < 3) {
                if (which == 1) v *= kscale;
                int b = m >> 9, pos = m & 511, h = n >> 5, d = n & 31;
                float* dst = (which==0) ? g_q : (which==1) ? g_k : g_v;
                dst[((size_t)(b*NH + h)*LSEQ + pos)*HD + d] = v;
            } else {
                v = 1.f / (1.f + __expf(-(v + bg[n])));
                g_gate[(size_t)m*DG + n] = v;
            }
        }
    }
}

// ---------------- fused LN(bias) @ Wb -> pair bias in [b,h,q,k] ----------------
// One warp per row. lane = (s = l>>3, li = l&7).
// Row data loaded redundantly across subs (4 LDG.128, broadcast dedup -> 4 wavefronts).
// Each sub computes dots for 2 heads only -> per-lane weight slice fits in 16 u64 REGISTERS
// (no shared-memory weight reads at all -> removes R3's crossbar bottleneck).
// Reductions: pairing butterfly (3 SHFL for dots) + 6 SHFL for stats.
__global__ void __launch_bounds__(256) pair_ln(const float* __restrict__ bias) {
    int tid = threadIdx.x;
    int l  = tid & 31;
    int li = l & 7;
    int s  = l >> 3;            // 0..3 -> heads 2s, 2s+1
    int h0 = 2*s, h1 = 2*s+1;
    int b0 = l & 1;
    int myh = h0 + b0;

    // weight registers: w0/w1[2j],[2j+1] cover floats j*32 + li*4 .. +3 of heads h0,h1
    unsigned long long w0[8], w1[8];
    {
        const ulonglong2* wp0 = (const ulonglong2*)(g_wgt + h0*DB);
        const ulonglong2* wp1 = (const ulonglong2*)(g_wgt + h1*DB);
#pragma unroll
        for (int j = 0; j < 4; j++) {
            ulonglong2 a = wp0[j*8 + li];
            ulonglong2 b = wp1[j*8 + li];
            w0[2*j] = a.x; w0[2*j+1] = a.y;
            w1[2*j] = b.x; w1[2*j+1] = b.y;
        }
    }
    float cwv = g_cw[myh];
    float bbv = g_bb[myh];
    size_t houts = (size_t)myh * (LSEQ*LSEQ);

    // 2048 blocks * 8 warps = 16384 warps, 32 consecutive rows each
    int gw = blockIdx.x * 8 + (tid >> 5);
    unsigned row0 = (unsigned)gw * 32u;

    for (int it = 0; it < 32; it++) {
        unsigned row = row0 + it;
        const char* rp = (const char*)(bias + (size_t)row * DB);
        unsigned long long xv[8];
        ldcs2(rp + (li     )*16, xv[0], xv[1]);
        ldcs2(rp + (li +  8)*16, xv[2], xv[3]);
        ldcs2(rp + (li + 16)*16, xv[4], xv[5]);
        ldcs2(rp + (li + 24)*16, xv[6], xv[7]);

        // stats (redundant across subs; reduced over li only)
        unsigned long long s1p = xv[0];
        unsigned long long s2p = 0ull;
        ffma2(s2p, xv[0], xv[0]);
#pragma unroll
        for (int j = 1; j < 8; j++) {
            fadd2(s1p, xv[j]);
            ffma2(s2p, xv[j], xv[j]);
        }
        // two head-dots
        unsigned long long a0 = 0ull, a1 = 0ull;
#pragma unroll
        for (int j = 0; j < 8; j++) {
            ffma2(a0, xv[j], w0[j]);
            ffma2(a1, xv[j], w1[j]);
        }
        float2 u;
        u = unpack2(s1p); float s1 = u.x + u.y;
        u = unpack2(s2p); float s2 = u.x + u.y;
        u = unpack2(a0);  float d0 = u.x + u.y;
        u = unpack2(a1);  float d1 = u.x + u.y;

        // stats: butterfly over li (bits 0..2)
#pragma unroll
        for (int off = 4; off; off >>= 1) {
            s1 += __shfl_xor_sync(0xffffffffu, s1, off);
            s2 += __shfl_xor_sync(0xffffffffu, s2, off);
        }
        // dots: pairing round (off=1) then same-head adds (off=2,4)
        float send = b0 ? d0 : d1;
        float dd   = (b0 ? d1 : d0) + __shfl_xor_sync(0xffffffffu, send, 1);
        dd += __shfl_xor_sync(0xffffffffu, dd, 2);
        dd += __shfl_xor_sync(0xffffffffu, dd, 4);

        float mu   = s1 * (1.f/128.f);
        float var  = fmaf(s2, 1.f/128.f, -mu*mu);
        float rstd = rsqrtf(var + 1e-5f);

        if ((l & 6) == 0) {   // lanes 0,1,8,9,16,17,24,25 -> heads 0..7
            float val = fmaf(rstd, dd - mu*cwv, bbv);
            unsigned bq  = row >> 18;        // batch
            unsigned low = row & 262143u;    // q*512 + k
            g_pb[(size_t)bq * (NH*(size_t)LSEQ*LSEQ) + houts + low] = val;
        }
    }
}

// ---------------- flash-style attention + gate ----------------
// block: 128 threads, 16 q rows; thread = (ty 0..15: 1 q row, tx 0..7)
// Ps stride padded to 68 (the stride-64 version is a 16-way LDS conflict).
__global__ void __launch_bounds__(128) attn_kernel() {
    __shared__ __align__(16) float Qs[16*36];
    __shared__ __align__(16) float Ks[64*36];
    __shared__ __align__(16) float Vs[64*32];
    __shared__ __align__(16) float Ps[16*68];
    int tid = threadIdx.x;
    int bh = blockIdx.x >> 5;              // 512 blocks = 16 bh * 32 q-tiles
    int q0 = (blockIdx.x & 31) * 16;
    const float* Qg = g_q + (size_t)bh * LSEQ * HD;
    const float* Kg = g_k + (size_t)bh * LSEQ * HD;
    const float* Vg = g_v + (size_t)bh * LSEQ * HD;
    {
        int r = tid >> 3, c = tid & 7;
        *(float4*)&Qs[r*36 + c*4] = *(const float4*)(Qg + (size_t)(q0+r)*HD + c*4);
    }
    int ty = tid >> 3, tx = tid & 7;
    const float* pb = g_pb + ((size_t)bh * LSEQ + q0 + ty) * LSEQ;
    float m = __int_as_float(0xff800000u);
    float lsum = 0.f;
    float acc[4] = {0,0,0,0};

    for (int kt = 0; kt < LSEQ; kt += 64) {
        __syncthreads();
        for (int i = tid; i < 512; i += 128) {
            int r = i >> 3, c = i & 7;
            *(float4*)&Ks[r*36 + c*4] = *(const float4*)(Kg + (size_t)(kt+r)*HD + c*4);
        }
        for (int i = tid; i < 512; i += 128) {
            int r = i >> 3, c = i & 7;
            *(float4*)&Vs[r*32 + c*4] = *(const float4*)(Vg + (size_t)(kt+r)*HD + c*4);
        }
        __syncthreads();
        float sv[8];
#pragma unroll
        for (int j = 0; j < 8; j++) sv[j] = pb[kt + tx + 8*j];
#pragma unroll
        for (int d4 = 0; d4 < 8; d4++) {
            float4 a = *(float4*)&Qs[ty*36 + d4*4];
#pragma unroll
            for (int j = 0; j < 8; j++) {
                float4 kv = *(float4*)&Ks[(tx + 8*j)*36 + d4*4];
                sv[j] = fmaf(a.x,kv.x, fmaf(a.y,kv.y, fmaf(a.z,kv.z, fmaf(a.w,kv.w, sv[j]))));
            }
        }
        float mx = sv[0];
#pragma unroll
        for (int j = 1; j < 8; j++) mx = fmaxf(mx, sv[j]);
#pragma unroll
        for (int off = 4; off; off >>= 1)
            mx = fmaxf(mx, __shfl_xor_sync(0xffffffffu, mx, off));
        float mn = fmaxf(m, mx);
        float sc = __expf(m - mn);
        float sum = 0.f;
#pragma unroll
        for (int j = 0; j < 8; j++) { sv[j] = __expf(sv[j] - mn); sum += sv[j]; }
#pragma unroll
        for (int off = 4; off; off >>= 1)
            sum += __shfl_xor_sync(0xffffffffu, sum, off);
        lsum = lsum*sc + sum;
        m = mn;
#pragma unroll
        for (int j = 0; j < 4; j++) acc[j] *= sc;
#pragma unroll
        for (int j = 0; j < 8; j++) Ps[ty*68 + tx + 8*j] = sv[j];
        __syncthreads();
#pragma unroll
        for (int k4 = 0; k4 < 16; k4++) {
            float4 pa = *(float4*)&Ps[ty*68 + k4*4];
            float4 va = *(float4*)&Vs[(k4*4+0)*32 + tx*4];
            float4 vb = *(float4*)&Vs[(k4*4+1)*32 + tx*4];
            float4 vc = *(float4*)&Vs[(k4*4+2)*32 + tx*4];
            float4 vd = *(float4*)&Vs[(k4*4+3)*32 + tx*4];
            acc[0]=fmaf(pa.x,va.x,acc[0]); acc[1]=fmaf(pa.x,va.y,acc[1]); acc[2]=fmaf(pa.x,va.z,acc[2]); acc[3]=fmaf(pa.x,va.w,acc[3]);
            acc[0]=fmaf(pa.y,vb.x,acc[0]); acc[1]=fmaf(pa.y,vb.y,acc[1]); acc[2]=fmaf(pa.y,vb.z,acc[2]); acc[3]=fmaf(pa.y,vb.w,acc[3]);
            acc[0]=fmaf(pa.z,vc.x,acc[0]); acc[1]=fmaf(pa.z,vc.y,acc[1]); acc[2]=fmaf(pa.z,vc.z,acc[2]); acc[3]=fmaf(pa.z,vc.w,acc[3]);
            acc[0]=fmaf(pa.w,vd.x,acc[0]); acc[1]=fmaf(pa.w,vd.y,acc[1]); acc[2]=fmaf(pa.w,vd.z,acc[2]); acc[3]=fmaf(pa.w,vd.w,acc[3]);
        }
    }
    float inv = 1.f / lsum;
    int b = bh >> 3, h = bh & 7;
    int mrow = b * LSEQ + q0 + ty;
    float4 g = *(const float4*)(g_gate + (size_t)mrow * DG + h*HD + tx*4);
    float4 o = make_float4(acc[0]*inv*g.x, acc[1]*inv*g.y, acc[2]*inv*g.z, acc[3]*inv*g.w);
    *(float4*)(g_hid + (size_t)mrow*DG + h*HD + tx*4) = o;
}

// ---------------- final GEMM: hid @ Wout + bout ----------------
__global__ void __launch_bounds__(256) gemm_out(const float* __restrict__ Wout,
                                                const float* __restrict__ bout,
                                                float* __restrict__ out) {
    __shared__ __align__(16) float Ast[16*68];
    __shared__ __align__(16) float Bs [16*68];
    int tid = threadIdx.x;
    int bm = blockIdx.y * 64;
    int bn = blockIdx.x * 64;
    int ty = tid >> 4, tx = tid & 15;
    int ar = tid >> 2, ac4 = tid & 3;
    int br = tid >> 4, bc4 = tid & 15;
    float acc[4][4] = {};
    for (int kb = 0; kb < 256; kb += 16) {
        float4 av = *(const float4*)(g_hid + (size_t)(bm+ar)*256 + kb + ac4*4);
        Ast[(ac4*4+0)*68 + ar] = av.x;
        Ast[(ac4*4+1)*68 + ar] = av.y;
        Ast[(ac4*4+2)*68 + ar] = av.z;
        Ast[(ac4*4+3)*68 + ar] = av.w;
        *(float4*)&Bs[br*68 + bc4*4] = *(const float4*)(Wout + (size_t)(kb+br)*256 + bn + bc4*4);
        __syncthreads();
#pragma unroll
        for (int k = 0; k < 16; k++) {
            float4 a = *(float4*)&Ast[k*68 + ty*4];
            float4 b = *(float4*)&Bs [k*68 + tx*4];
            acc[0][0]=fmaf(a.x,b.x,acc[0][0]); acc[0][1]=fmaf(a.x,b.y,acc[0][1]);
            acc[0][2]=fmaf(a.x,b.z,acc[0][2]); acc[0][3]=fmaf(a.x,b.w,acc[0][3]);
            acc[1][0]=fmaf(a.y,b.x,acc[1][0]); acc[1][1]=fmaf(a.y,b.y,acc[1][1]);
            acc[1][2]=fmaf(a.y,b.z,acc[1][2]); acc[1][3]=fmaf(a.y,b.w,acc[1][3]);
            acc[2][0]=fmaf(a.z,b.x,acc[2][0]); acc[2][1]=fmaf(a.z,b.y,acc[2][1]);
            acc[2][2]=fmaf(a.z,b.z,acc[2][2]); acc[2][3]=fmaf(a.z,b.w,acc[2][3]);
            acc[3][0]=fmaf(a.w,b.x,acc[3][0]); acc[3][1]=fmaf(a.w,b.y,acc[3][1]);
            acc[3][2]=fmaf(a.w,b.z,acc[3][2]); acc[3][3]=fmaf(a.w,b.w,acc[3][3]);
        }
        __syncthreads();
    }
#pragma unroll
    for (int i = 0; i < 4; i++) {
#pragma unroll
        for (int j = 0; j < 4; j++) {
            int m = bm + ty*4 + i;
            int n = bn + tx*4 + j;
            out[(size_t)m*256 + n] = acc[i][j] + bout[n];
        }
    }
}

// ---------------- launch ----------------
extern "C" void kernel_launch(void* const* d_in, const int* in_sizes, int n_in,
                              void* d_out, int out_size) {
    const float* x       = (const float*)d_in[0];
    const float* bias    = (const float*)d_in[1];
    const float* g_gamma = (const float*)d_in[2];
    const float* g_beta  = (const float*)d_in[3];
    const float* b_gamma = (const float*)d_in[4];
    const float* b_beta  = (const float*)d_in[5];
    const float* Wq      = (const float*)d_in[6];
    const float* Wk      = (const float*)d_in[7];
    const float* Wv      = (const float*)d_in[8];
    const float* Wb      = (const float*)d_in[9];
    const float* Wg      = (const float*)d_in[10];
    const float* bg      = (const float*)d_in[11];
    const float* Wout    = (const float*)d_in[12];
    const float* bout    = (const float*)d_in[13];
    float* out = (float*)d_out;

    prep_wb<<<1, 128>>>(b_gamma, b_beta, Wb);
    ln_x<<<256, 128>>>(x, g_gamma, g_beta);
    gemm_qkvg<<<dim3(16, 16), 256>>>(Wq, Wk, Wv, Wg, bg);
    pair_ln<<<2048, 256>>>(bias);
    attn_kernel<<<512, 128>>>();
    gemm_out<<<dim3(4, 16), 256>>>(Wout, bout, out);
}

// round 6
// speedup vs baseline: 1.0639x; 1.0639x over previous
#include <cuda_runtime.h>
#include <math.h>

#define LSEQ 512
#define BATCH 2
#define DG 256
#define DB 128
#define NH 8
#define HD 32
#define BH (BATCH*NH)   // 16

// ---------------- scratch (device globals; no allocation allowed) ----------------
__device__ float g_xn[BATCH*LSEQ*DG];        // LN(x)                [1024][256]
__device__ float g_q[BH*LSEQ*HD];            // [b*h][l][32]
__device__ float g_k[BH*LSEQ*HD];            // pre-scaled by 1/sqrt(32)
__device__ float g_v[BH*LSEQ*HD];
__device__ float g_gate[BATCH*LSEQ*DG];      // sigmoid(xn@Wg+bg)    [1024][256]
__device__ float g_pb[(size_t)BH*LSEQ*LSEQ]; // pair bias            [b*h][q][k]
__device__ float g_hid[BATCH*LSEQ*DG];       // gate * attn_out      [1024][256]
__device__ float g_wgt[NH*DB];               // b_gamma[i]*Wb[i][h]  [h][i]
__device__ float g_cw[NH];                   // sum_i b_gamma[i]*Wb[i][h]
__device__ float g_bb[NH];                   // b_beta @ Wb[:,h]

// packed f32x2 helpers (sm_10x FFMA2 path — PTX only)
__device__ __forceinline__ void ffma2(unsigned long long& acc,
                                      unsigned long long a,
                                      unsigned long long b) {
    asm("fma.rn.f32x2 %0, %1, %2, %0;" : "+l"(acc) : "l"(a), "l"(b));
}
__device__ __forceinline__ void fadd2(unsigned long long& acc, unsigned long long a) {
    asm("add.rn.f32x2 %0, %1, %0;" : "+l"(acc) : "l"(a));
}
__device__ __forceinline__ float2 unpack2(unsigned long long v) {
    float2 r;
    asm("mov.b64 {%0, %1}, %2;" : "=f"(r.x), "=f"(r.y) : "l"(v));
    return r;
}

// ---------------- prep: fold b_gamma/b_beta into Wb ----------------
__global__ void prep_wb(const float* __restrict__ b_gamma,
                        const float* __restrict__ b_beta,
                        const float* __restrict__ Wb) {
    __shared__ float sc[NH][DB];
    __shared__ float sb[NH][DB];
    int i = threadIdx.x;            // 128 threads
    float g = b_gamma[i];
    float bt = b_beta[i];
#pragma unroll
    for (int h = 0; h < NH; h++) {
        float w = Wb[i*NH + h];
        g_wgt[h*DB + i] = g * w;
        sc[h][i] = g * w;
        sb[h][i] = bt * w;
    }
    __syncthreads();
    if (i < NH) {
        float a = 0.f, b2 = 0.f;
        for (int j = 0; j < DB; j++) { a += sc[i][j]; b2 += sb[i][j]; }
        g_cw[i] = a;
        g_bb[i] = b2;
    }
}

// ---------------- LN over x rows (dim 256), warp per row ----------------
__global__ void __launch_bounds__(128) ln_x(const float* __restrict__ x,
                                            const float* __restrict__ gamma,
                                            const float* __restrict__ beta) {
    int warp = threadIdx.x >> 5, lane = threadIdx.x & 31;
    int row = blockIdx.x * 4 + warp;           // 1024 rows, grid 256
    const float* rp = x + (size_t)row * DG;
    float4 v0 = *(const float4*)(rp + lane*4);
    float4 v1 = *(const float4*)(rp + 128 + lane*4);
    float s1 = v0.x+v0.y+v0.z+v0.w + v1.x+v1.y+v1.z+v1.w;
    float s2 = v0.x*v0.x+v0.y*v0.y+v0.z*v0.z+v0.w*v0.w
             + v1.x*v1.x+v1.y*v1.y+v1.z*v1.z+v1.w*v1.w;
#pragma unroll
    for (int off = 16; off; off >>= 1) {
        s1 += __shfl_xor_sync(0xffffffffu, s1, off);
        s2 += __shfl_xor_sync(0xffffffffu, s2, off);
    }
    float mu = s1 * (1.f/256.f);
    float var = s2 * (1.f/256.f) - mu*mu;
    float rstd = rsqrtf(var + 1e-5f);
    float4 gm0 = *(const float4*)(gamma + lane*4);
    float4 gm1 = *(const float4*)(gamma + 128 + lane*4);
    float4 bt0 = *(const float4*)(beta + lane*4);
    float4 bt1 = *(const float4*)(beta + 128 + lane*4);
    float4 o0, o1;
    o0.x = (v0.x-mu)*rstd*gm0.x + bt0.x; o0.y = (v0.y-mu)*rstd*gm0.y + bt0.y;
    o0.z = (v0.z-mu)*rstd*gm0.z + bt0.z; o0.w = (v0.w-mu)*rstd*gm0.w + bt0.w;
    o1.x = (v1.x-mu)*rstd*gm1.x + bt1.x; o1.y = (v1.y-mu)*rstd*gm1.y + bt1.y;
    o1.z = (v1.z-mu)*rstd*gm1.z + bt1.z; o1.w = (v1.w-mu)*rstd*gm1.w + bt1.w;
    *(float4*)(g_xn + (size_t)row*DG + lane*4) = o0;
    *(float4*)(g_xn + (size_t)row*DG + 128 + lane*4) = o1;
}

// ---------------- fused GEMM: xn @ [Wq|Wk|Wv|Wg] (M=1024, N=1024, K=256) ----------------
__global__ void __launch_bounds__(256) gemm_qkvg(const float* __restrict__ Wq,
                                                 const float* __restrict__ Wk,
                                                 const float* __restrict__ Wv,
                                                 const float* __restrict__ Wg,
                                                 const float* __restrict__ bg) {
    __shared__ __align__(16) float Ast[16*68];   // [k][m] transposed, padded
    __shared__ __align__(16) float Bs [16*68];   // [k][n], padded
    int tid = threadIdx.x;
    int bm = blockIdx.y * 64;
    int bn_g = blockIdx.x * 64;          // 0..1023
    int which = bn_g >> 8;               // 0:Q 1:K 2:V 3:G
    int bn = bn_g & 255;
    const float* W = (which==0) ? Wq : (which==1) ? Wk : (which==2) ? Wv : Wg;
    int ty = tid >> 4, tx = tid & 15;
    int ar = tid >> 2, ac4 = tid & 3;
    int br = tid >> 4, bc4 = tid & 15;
    float acc[4][4] = {};
    for (int kb = 0; kb < 256; kb += 16) {
        float4 av = *(const float4*)(g_xn + (size_t)(bm+ar)*256 + kb + ac4*4);
        Ast[(ac4*4+0)*68 + ar] = av.x;
        Ast[(ac4*4+1)*68 + ar] = av.y;
        Ast[(ac4*4+2)*68 + ar] = av.z;
        Ast[(ac4*4+3)*68 + ar] = av.w;
        *(float4*)&Bs[br*68 + bc4*4] = *(const float4*)(W + (size_t)(kb+br)*256 + bn + bc4*4);
        __syncthreads();
#pragma unroll
        for (int k = 0; k < 16; k++) {
            float4 a = *(float4*)&Ast[k*68 + ty*4];
            float4 b = *(float4*)&Bs [k*68 + tx*4];
            acc[0][0]=fmaf(a.x,b.x,acc[0][0]); acc[0][1]=fmaf(a.x,b.y,acc[0][1]);
            acc[0][2]=fmaf(a.x,b.z,acc[0][2]); acc[0][3]=fmaf(a.x,b.w,acc[0][3]);
            acc[1][0]=fmaf(a.y,b.x,acc[1][0]); acc[1][1]=fmaf(a.y,b.y,acc[1][1]);
            acc[1][2]=fmaf(a.y,b.z,acc[1][2]); acc[1][3]=fmaf(a.y,b.w,acc[1][3]);
            acc[2][0]=fmaf(a.z,b.x,acc[2][0]); acc[2][1]=fmaf(a.z,b.y,acc[2][1]);
            acc[2][2]=fmaf(a.z,b.z,acc[2][2]); acc[2][3]=fmaf(a.z,b.w,acc[2][3]);
            acc[3][0]=fmaf(a.w,b.x,acc[3][0]); acc[3][1]=fmaf(a.w,b.y,acc[3][1]);
            acc[3][2]=fmaf(a.w,b.z,acc[3][2]); acc[3][3]=fmaf(a.w,b.w,acc[3][3]);
        }
        __syncthreads();
    }
    const float kscale = 0.17677669529663687f; // 1/sqrt(32)
#pragma unroll
    for (int i = 0; i < 4; i++) {
#pragma unroll
        for (int j = 0; j < 4; j++) {
            int m = bm + ty*4 + i;
            int n = bn + tx*4 + j;
            float v = acc[i][j];
            if (which < 3) {
                if (which == 1) v *= kscale;
                int b = m >> 9, pos = m & 511, h = n >> 5, d = n & 31;
                float* dst = (which==0) ? g_q : (which==1) ? g_k : g_v;
                dst[((size_t)(b*NH + h)*LSEQ + pos)*HD + d] = v;
            } else {
                v = 1.f / (1.f + __expf(-(v + bg[n])));
                g_gate[(size_t)m*DG + n] = v;
            }
        }
    }
}

// ---------------- fused LN(bias) @ Wb -> pair bias in [b,h,q,k] ----------------
// One-shot warps (R3 structure): warp = 4 rows (sub = row), lane li owns the
// contiguous 16B chunks j*128B + li*16B of its row. Weight LDS are conflict-free
// (chunk index h*32+j*8+li -> mod 8 = li) and broadcast across subs.
// NEW: results staged in padded smem and re-emitted as fully-coalesced stores
// (head = warp, 32 consecutive k per block) -> 8x fewer store wavefronts, 2x
// fewer store sectors than the scattered 8-plane STG.
__global__ void __launch_bounds__(256) pair_ln(const float* __restrict__ bias) {
    __shared__ __align__(16) float swg[NH*DB];
    __shared__ float scw[NH], sbb[NH];
    __shared__ float sval[8*9*4];   // [warp][head(pad 9)][sub]
    int tid = threadIdx.x;
    for (int i = tid; i < NH*DB; i += 256) swg[i] = g_wgt[i];
    if (tid < NH) { scw[tid] = g_cw[tid]; sbb[tid] = g_bb[tid]; }
    __syncthreads();
    int warp = tid >> 5, lane = tid & 31;
    int sub = lane >> 3, li = lane & 7;
    unsigned row = blockIdx.x * 32u + warp * 4u + sub;   // < 524288
    const ulonglong2* rp = (const ulonglong2*)(bias + (size_t)row * DB);

    // load this lane's 16 elements: chunks j*8 + li
    unsigned long long xv[8];
#pragma unroll
    for (int j = 0; j < 4; j++) {
        ulonglong2 t = rp[j*8 + li];
        xv[2*j]   = t.x;
        xv[2*j+1] = t.y;
    }

    // stats (packed)
    unsigned long long s1p = xv[0], s2p = 0ull;
    ffma2(s2p, xv[0], xv[0]);
#pragma unroll
    for (int j = 1; j < 8; j++) {
        fadd2(s1p, xv[j]);
        ffma2(s2p, xv[j], xv[j]);
    }

    // 8 dot products vs folded weights (conflict-free broadcast LDS)
    const ulonglong2* wsp = (const ulonglong2*)swg;  // index: h*32 + j*8 + li
    unsigned long long acc[NH];
#pragma unroll
    for (int h = 0; h < NH; h++) {
        unsigned long long a = 0ull;
#pragma unroll
        for (int j = 0; j < 4; j++) {
            ulonglong2 w = wsp[h*32 + j*8 + li];
            ffma2(a, xv[2*j],   w.x);
            ffma2(a, xv[2*j+1], w.y);
        }
        acc[h] = a;
    }

    float2 t1 = unpack2(s1p);
    float2 t2 = unpack2(s2p);
    float s1 = t1.x + t1.y;
    float s2 = t2.x + t2.y;
    float d[NH];
#pragma unroll
    for (int h = 0; h < NH; h++) {
        float2 td = unpack2(acc[h]);
        d[h] = td.x + td.y;
    }

    // reduce across the 8 lanes of this row
#pragma unroll
    for (int off = 4; off; off >>= 1) {
        s1 += __shfl_xor_sync(0xffffffffu, s1, off);
        s2 += __shfl_xor_sync(0xffffffffu, s2, off);
#pragma unroll
        for (int h = 0; h < NH; h++) d[h] += __shfl_xor_sync(0xffffffffu, d[h], off);
    }

    float mu = s1 * (1.f/128.f);
    float var = fmaf(s2, 1.f/128.f, -mu*mu);
    float rstd = rsqrtf(var + 1e-5f);

    // lane li holds head li's value for row (sub)
    float dh = d[0];
#pragma unroll
    for (int h = 1; h < NH; h++) dh = (li == h) ? d[h] : dh;
    float val = fmaf(rstd, dh - mu*scw[li], sbb[li]);

    // stage: sval[warp][li][sub]  (write banks: li*4+sub distinct -> conflict-free)
    sval[warp*36 + li*4 + sub] = val;
    __syncthreads();

    // coalesced emit: head = warp index of emitting thread, k-run of 32
    int h  = tid >> 5;
    int kk = tid & 31;
    unsigned rowk = blockIdx.x * 32u + kk;
    unsigned bq = rowk >> 18;
    unsigned q  = (rowk >> 9) & 511u;
    unsigned k  = rowk & 511u;
    float v = sval[(kk>>2)*36 + h*4 + (kk&3)];   // banks 4*(kk>>2)+(kk&3) distinct
    g_pb[((size_t)(bq*NH + h)*LSEQ + q)*LSEQ + k] = v;
}

// ---------------- flash-style attention + gate ----------------
// block: 128 threads, 16 q rows; thread = (ty 0..15: 1 q row, tx 0..7)
// Ps stride padded to 68 (the stride-64 version is a 16-way LDS conflict).
__global__ void __launch_bounds__(128) attn_kernel() {
    __shared__ __align__(16) float Qs[16*36];
    __shared__ __align__(16) float Ks[64*36];
    __shared__ __align__(16) float Vs[64*32];
    __shared__ __align__(16) float Ps[16*68];
    int tid = threadIdx.x;
    int bh = blockIdx.x >> 5;              // 512 blocks = 16 bh * 32 q-tiles
    int q0 = (blockIdx.x & 31) * 16;
    const float* Qg = g_q + (size_t)bh * LSEQ * HD;
    const float* Kg = g_k + (size_t)bh * LSEQ * HD;
    const float* Vg = g_v + (size_t)bh * LSEQ * HD;
    {
        int r = tid >> 3, c = tid & 7;
        *(float4*)&Qs[r*36 + c*4] = *(const float4*)(Qg + (size_t)(q0+r)*HD + c*4);
    }
    int ty = tid >> 3, tx = tid & 7;
    const float* pb = g_pb + ((size_t)bh * LSEQ + q0 + ty) * LSEQ;
    float m = __int_as_float(0xff800000u);
    float lsum = 0.f;
    float acc[4] = {0,0,0,0};

    for (int kt = 0; kt < LSEQ; kt += 64) {
        __syncthreads();
        for (int i = tid; i < 512; i += 128) {
            int r = i >> 3, c = i & 7;
            *(float4*)&Ks[r*36 + c*4] = *(const float4*)(Kg + (size_t)(kt+r)*HD + c*4);
        }
        for (int i = tid; i < 512; i += 128) {
            int r = i >> 3, c = i & 7;
            *(float4*)&Vs[r*32 + c*4] = *(const float4*)(Vg + (size_t)(kt+r)*HD + c*4);
        }
        __syncthreads();
        float sv[8];
#pragma unroll
        for (int j = 0; j < 8; j++) sv[j] = pb[kt + tx + 8*j];
#pragma unroll
        for (int d4 = 0; d4 < 8; d4++) {
            float4 a = *(float4*)&Qs[ty*36 + d4*4];
#pragma unroll
            for (int j = 0; j < 8; j++) {
                float4 kv = *(float4*)&Ks[(tx + 8*j)*36 + d4*4];
                sv[j] = fmaf(a.x,kv.x, fmaf(a.y,kv.y, fmaf(a.z,kv.z, fmaf(a.w,kv.w, sv[j]))));
            }
        }
        float mx = sv[0];
#pragma unroll
        for (int j = 1; j < 8; j++) mx = fmaxf(mx, sv[j]);
#pragma unroll
        for (int off = 4; off; off >>= 1)
            mx = fmaxf(mx, __shfl_xor_sync(0xffffffffu, mx, off));
        float mn = fmaxf(m, mx);
        float sc = __expf(m - mn);
        float sum = 0.f;
#pragma unroll
        for (int j = 0; j < 8; j++) { sv[j] = __expf(sv[j] - mn); sum += sv[j]; }
#pragma unroll
        for (int off = 4; off; off >>= 1)
            sum += __shfl_xor_sync(0xffffffffu, sum, off);
        lsum = lsum*sc + sum;
        m = mn;
#pragma unroll
        for (int j = 0; j < 4; j++) acc[j] *= sc;
#pragma unroll
        for (int j = 0; j < 8; j++) Ps[ty*68 + tx + 8*j] = sv[j];
        __syncthreads();
#pragma unroll
        for (int k4 = 0; k4 < 16; k4++) {
            float4 pa = *(float4*)&Ps[ty*68 + k4*4];
            float4 va = *(float4*)&Vs[(k4*4+0)*32 + tx*4];
            float4 vb = *(float4*)&Vs[(k4*4+1)*32 + tx*4];
            float4 vc = *(float4*)&Vs[(k4*4+2)*32 + tx*4];
            float4 vd = *(float4*)&Vs[(k4*4+3)*32 + tx*4];
            acc[0]=fmaf(pa.x,va.x,acc[0]); acc[1]=fmaf(pa.x,va.y,acc[1]); acc[2]=fmaf(pa.x,va.z,acc[2]); acc[3]=fmaf(pa.x,va.w,acc[3]);
            acc[0]=fmaf(pa.y,vb.x,acc[0]); acc[1]=fmaf(pa.y,vb.y,acc[1]); acc[2]=fmaf(pa.y,vb.z,acc[2]); acc[3]=fmaf(pa.y,vb.w,acc[3]);
            acc[0]=fmaf(pa.z,vc.x,acc[0]); acc[1]=fmaf(pa.z,vc.y,acc[1]); acc[2]=fmaf(pa.z,vc.z,acc[2]); acc[3]=fmaf(pa.z,vc.w,acc[3]);
            acc[0]=fmaf(pa.w,vd.x,acc[0]); acc[1]=fmaf(pa.w,vd.y,acc[1]); acc[2]=fmaf(pa.w,vd.z,acc[2]); acc[3]=fmaf(pa.w,vd.w,acc[3]);
        }
    }
    float inv = 1.f / lsum;
    int b = bh >> 3, h = bh & 7;
    int mrow = b * LSEQ + q0 + ty;
    float4 g = *(const float4*)(g_gate + (size_t)mrow * DG + h*HD + tx*4);
    float4 o = make_float4(acc[0]*inv*g.x, acc[1]*inv*g.y, acc[2]*inv*g.z, acc[3]*inv*g.w);
    *(float4*)(g_hid + (size_t)mrow*DG + h*HD + tx*4) = o;
}

// ---------------- final GEMM: hid @ Wout + bout ----------------
__global__ void __launch_bounds__(256) gemm_out(const float* __restrict__ Wout,
                                                const float* __restrict__ bout,
                                                float* __restrict__ out) {
    __shared__ __align__(16) float Ast[16*68];
    __shared__ __align__(16) float Bs [16*68];
    int tid = threadIdx.x;
    int bm = blockIdx.y * 64;
    int bn = blockIdx.x * 64;
    int ty = tid >> 4, tx = tid & 15;
    int ar = tid >> 2, ac4 = tid & 3;
    int br = tid >> 4, bc4 = tid & 15;
    float acc[4][4] = {};
    for (int kb = 0; kb < 256; kb += 16) {
        float4 av = *(const float4*)(g_hid + (size_t)(bm+ar)*256 + kb + ac4*4);
        Ast[(ac4*4+0)*68 + ar] = av.x;
        Ast[(ac4*4+1)*68 + ar] = av.y;
        Ast[(ac4*4+2)*68 + ar] = av.z;
        Ast[(ac4*4+3)*68 + ar] = av.w;
        *(float4*)&Bs[br*68 + bc4*4] = *(const float4*)(Wout + (size_t)(kb+br)*256 + bn + bc4*4);
        __syncthreads();
#pragma unroll
        for (int k = 0; k < 16; k++) {
            float4 a = *(float4*)&Ast[k*68 + ty*4];
            float4 b = *(float4*)&Bs [k*68 + tx*4];
            acc[0][0]=fmaf(a.x,b.x,acc[0][0]); acc[0][1]=fmaf(a.x,b.y,acc[0][1]);
            acc[0][2]=fmaf(a.x,b.z,acc[0][2]); acc[0][3]=fmaf(a.x,b.w,acc[0][3]);
            acc[1][0]=fmaf(a.y,b.x,acc[1][0]); acc[1][1]=fmaf(a.y,b.y,acc[1][1]);
            acc[1][2]=fmaf(a.y,b.z,acc[1][2]); acc[1][3]=fmaf(a.y,b.w,acc[1][3]);
            acc[2][0]=fmaf(a.z,b.x,acc[2][0]); acc[2][1]=fmaf(a.z,b.y,acc[2][1]);
            acc[2][2]=fmaf(a.z,b.z,acc[2][2]); acc[2][3]=fmaf(a.z,b.w,acc[2][3]);
            acc[3][0]=fmaf(a.w,b.x,acc[3][0]); acc[3][1]=fmaf(a.w,b.y,acc[3][1]);
            acc[3][2]=fmaf(a.w,b.z,acc[3][2]); acc[3][3]=fmaf(a.w,b.w,acc[3][3]);
        }
        __syncthreads();
    }
#pragma unroll
    for (int i = 0; i < 4; i++) {
#pragma unroll
        for (int j = 0; j < 4; j++) {
            int m = bm + ty*4 + i;
            int n = bn + tx*4 + j;
            out[(size_t)m*256 + n] = acc[i][j] + bout[n];
        }
    }
}

// ---------------- launch ----------------
extern "C" void kernel_launch(void* const* d_in, const int* in_sizes, int n_in,
                              void* d_out, int out_size) {
    const float* x       = (const float*)d_in[0];
    const float* bias    = (const float*)d_in[1];
    const float* g_gamma = (const float*)d_in[2];
    const float* g_beta  = (const float*)d_in[3];
    const float* b_gamma = (const float*)d_in[4];
    const float* b_beta  = (const float*)d_in[5];
    const float* Wq      = (const float*)d_in[6];
    const float* Wk      = (const float*)d_in[7];
    const float* Wv      = (const float*)d_in[8];
    const float* Wb      = (const float*)d_in[9];
    const float* Wg      = (const float*)d_in[10];
    const float* bg      = (const float*)d_in[11];
    const float* Wout    = (const float*)d_in[12];
    const float* bout    = (const float*)d_in[13];
    float* out = (float*)d_out;

    prep_wb<<<1, 128>>>(b_gamma, b_beta, Wb);
    ln_x<<<256, 128>>>(x, g_gamma, g_beta);
    gemm_qkvg<<<dim3(16, 16), 256>>>(Wq, Wk, Wv, Wg, bg);
    pair_ln<<<16384, 256>>>(bias);
    attn_kernel<<<512, 128>>>();
    gemm_out<<<dim3(4, 16), 256>>>(Wout, bout, out);
}

// round 7
// speedup vs baseline: 1.1551x; 1.0857x over previous
#include <cuda_runtime.h>
#include <math.h>

#define LSEQ 512
#define BATCH 2
#define DG 256
#define DB 128
#define NH 8
#define HD 32
#define BH (BATCH*NH)   // 16

// ---------------- scratch (device globals; no allocation allowed) ----------------
__device__ float g_xn[BATCH*LSEQ*DG];        // LN(x)                [1024][256]
__device__ float g_q[BH*LSEQ*HD];            // [b*h][l][32]
__device__ float g_k[BH*LSEQ*HD];            // pre-scaled by 1/sqrt(32)
__device__ float g_v[BH*LSEQ*HD];
__device__ float g_gate[BATCH*LSEQ*DG];      // sigmoid(xn@Wg+bg)    [1024][256]
__device__ float g_pb[(size_t)BH*LSEQ*LSEQ]; // pair bias            [b*h][q][k]
__device__ float g_hid[BATCH*LSEQ*DG];       // gate * attn_out      [1024][256]
__device__ float g_wgt[NH*DB];               // b_gamma[i]*Wb[i][h]  [h][i]
__device__ float g_cw[NH];                   // sum_i b_gamma[i]*Wb[i][h]
__device__ float g_bb[NH];                   // b_beta @ Wb[:,h]

// packed f32x2 helpers (sm_10x FFMA2 path — PTX only)
__device__ __forceinline__ void ffma2(unsigned long long& acc,
                                      unsigned long long a,
                                      unsigned long long b) {
    asm("fma.rn.f32x2 %0, %1, %2, %0;" : "+l"(acc) : "l"(a), "l"(b));
}
__device__ __forceinline__ void fadd2(unsigned long long& acc, unsigned long long a) {
    asm("add.rn.f32x2 %0, %1, %0;" : "+l"(acc) : "l"(a));
}
__device__ __forceinline__ float2 unpack2(unsigned long long v) {
    float2 r;
    asm("mov.b64 {%0, %1}, %2;" : "=f"(r.x), "=f"(r.y) : "l"(v));
    return r;
}

// ---------------- prep: fold b_gamma/b_beta into Wb ----------------
__global__ void prep_wb(const float* __restrict__ b_gamma,
                        const float* __restrict__ b_beta,
                        const float* __restrict__ Wb) {
    __shared__ float sc[NH][DB];
    __shared__ float sb[NH][DB];
    int i = threadIdx.x;            // 128 threads
    float g = b_gamma[i];
    float bt = b_beta[i];
#pragma unroll
    for (int h = 0; h < NH; h++) {
        float w = Wb[i*NH + h];
        g_wgt[h*DB + i] = g * w;
        sc[h][i] = g * w;
        sb[h][i] = bt * w;
    }
    __syncthreads();
    if (i < NH) {
        float a = 0.f, b2 = 0.f;
        for (int j = 0; j < DB; j++) { a += sc[i][j]; b2 += sb[i][j]; }
        g_cw[i] = a;
        g_bb[i] = b2;
    }
}

// ---------------- LN over x rows (dim 256), warp per row ----------------
__global__ void __launch_bounds__(128) ln_x(const float* __restrict__ x,
                                            const float* __restrict__ gamma,
                                            const float* __restrict__ beta) {
    int warp = threadIdx.x >> 5, lane = threadIdx.x & 31;
    int row = blockIdx.x * 4 + warp;           // 1024 rows, grid 256
    const float* rp = x + (size_t)row * DG;
    float4 v0 = *(const float4*)(rp + lane*4);
    float4 v1 = *(const float4*)(rp + 128 + lane*4);
    float s1 = v0.x+v0.y+v0.z+v0.w + v1.x+v1.y+v1.z+v1.w;
    float s2 = v0.x*v0.x+v0.y*v0.y+v0.z*v0.z+v0.w*v0.w
             + v1.x*v1.x+v1.y*v1.y+v1.z*v1.z+v1.w*v1.w;
#pragma unroll
    for (int off = 16; off; off >>= 1) {
        s1 += __shfl_xor_sync(0xffffffffu, s1, off);
        s2 += __shfl_xor_sync(0xffffffffu, s2, off);
    }
    float mu = s1 * (1.f/256.f);
    float var = s2 * (1.f/256.f) - mu*mu;
    float rstd = rsqrtf(var + 1e-5f);
    float4 gm0 = *(const float4*)(gamma + lane*4);
    float4 gm1 = *(const float4*)(gamma + 128 + lane*4);
    float4 bt0 = *(const float4*)(beta + lane*4);
    float4 bt1 = *(const float4*)(beta + 128 + lane*4);
    float4 o0, o1;
    o0.x = (v0.x-mu)*rstd*gm0.x + bt0.x; o0.y = (v0.y-mu)*rstd*gm0.y + bt0.y;
    o0.z = (v0.z-mu)*rstd*gm0.z + bt0.z; o0.w = (v0.w-mu)*rstd*gm0.w + bt0.w;
    o1.x = (v1.x-mu)*rstd*gm1.x + bt1.x; o1.y = (v1.y-mu)*rstd*gm1.y + bt1.y;
    o1.z = (v1.z-mu)*rstd*gm1.z + bt1.z; o1.w = (v1.w-mu)*rstd*gm1.w + bt1.w;
    *(float4*)(g_xn + (size_t)row*DG + lane*4) = o0;
    *(float4*)(g_xn + (size_t)row*DG + 128 + lane*4) = o1;
}

// ---------------- fused GEMM: xn @ [Wq|Wk|Wv|Wg] (M=1024, N=1024, K=256) ----------------
__global__ void __launch_bounds__(256) gemm_qkvg(const float* __restrict__ Wq,
                                                 const float* __restrict__ Wk,
                                                 const float* __restrict__ Wv,
                                                 const float* __restrict__ Wg,
                                                 const float* __restrict__ bg) {
    __shared__ __align__(16) float Ast[16*68];   // [k][m] transposed, padded
    __shared__ __align__(16) float Bs [16*68];   // [k][n], padded
    int tid = threadIdx.x;
    int bm = blockIdx.y * 64;
    int bn_g = blockIdx.x * 64;          // 0..1023
    int which = bn_g >> 8;               // 0:Q 1:K 2:V 3:G
    int bn = bn_g & 255;
    const float* W = (which==0) ? Wq : (which==1) ? Wk : (which==2) ? Wv : Wg;
    int ty = tid >> 4, tx = tid & 15;
    int ar = tid >> 2, ac4 = tid & 3;
    int br = tid >> 4, bc4 = tid & 15;
    float acc[4][4] = {};
    for (int kb = 0; kb < 256; kb += 16) {
        float4 av = *(const float4*)(g_xn + (size_t)(bm+ar)*256 + kb + ac4*4);
        Ast[(ac4*4+0)*68 + ar] = av.x;
        Ast[(ac4*4+1)*68 + ar] = av.y;
        Ast[(ac4*4+2)*68 + ar] = av.z;
        Ast[(ac4*4+3)*68 + ar] = av.w;
        *(float4*)&Bs[br*68 + bc4*4] = *(const float4*)(W + (size_t)(kb+br)*256 + bn + bc4*4);
        __syncthreads();
#pragma unroll
        for (int k = 0; k < 16; k++) {
            float4 a = *(float4*)&Ast[k*68 + ty*4];
            float4 b = *(float4*)&Bs [k*68 + tx*4];
            acc[0][0]=fmaf(a.x,b.x,acc[0][0]); acc[0][1]=fmaf(a.x,b.y,acc[0][1]);
            acc[0][2]=fmaf(a.x,b.z,acc[0][2]); acc[0][3]=fmaf(a.x,b.w,acc[0][3]);
            acc[1][0]=fmaf(a.y,b.x,acc[1][0]); acc[1][1]=fmaf(a.y,b.y,acc[1][1]);
            acc[1][2]=fmaf(a.y,b.z,acc[1][2]); acc[1][3]=fmaf(a.y,b.w,acc[1][3]);
            acc[2][0]=fmaf(a.z,b.x,acc[2][0]); acc[2][1]=fmaf(a.z,b.y,acc[2][1]);
            acc[2][2]=fmaf(a.z,b.z,acc[2][2]); acc[2][3]=fmaf(a.z,b.w,acc[2][3]);
            acc[3][0]=fmaf(a.w,b.x,acc[3][0]); acc[3][1]=fmaf(a.w,b.y,acc[3][1]);
            acc[3][2]=fmaf(a.w,b.z,acc[3][2]); acc[3][3]=fmaf(a.w,b.w,acc[3][3]);
        }
        __syncthreads();
    }
    const float kscale = 0.17677669529663687f; // 1/sqrt(32)
#pragma unroll
    for (int i = 0; i < 4; i++) {
#pragma unroll
        for (int j = 0; j < 4; j++) {
            int m = bm + ty*4 + i;
            int n = bn + tx*4 + j;
            float v = acc[i][j];
            if (which < 3) {
                if (which == 1) v *= kscale;
                int b = m >> 9, pos = m & 511, h = n >> 5, d = n & 31;
                float* dst = (which==0) ? g_q : (which==1) ? g_k : g_v;
                dst[((size_t)(b*NH + h)*LSEQ + pos)*HD + d] = v;
            } else {
                v = 1.f / (1.f + __expf(-(v + bg[n])));
                g_gate[(size_t)m*DG + n] = v;
            }
        }
    }
}

// ---------------- fused LN(bias) @ Wb -> pair bias in [b,h,q,k] ----------------
// Warp = 8 rows: sub handles rows (base+sub) and (base+sub+4); lane li owns the
// contiguous 16B chunks of each row. Each weight LDS.128 now feeds FFMA2s for
// TWO rows -> weight crossbar cost halves to 16 cyc/row (was the L1 binder).
// Results staged in smem, re-emitted as coalesced 128B stores (head=warp set,
// 64-k run per block).
__global__ void __launch_bounds__(256) pair_ln(const float* __restrict__ bias) {
    __shared__ __align__(16) float swg[NH*DB];
    __shared__ float scw[NH], sbb[NH];
    __shared__ float sval[8*72];    // [warp][head*9 + subrow(0..7)]
    int tid = threadIdx.x;
    for (int i = tid; i < NH*DB; i += 256) swg[i] = g_wgt[i];
    if (tid < NH) { scw[tid] = g_cw[tid]; sbb[tid] = g_bb[tid]; }
    __syncthreads();
    int warp = tid >> 5, lane = tid & 31;
    int sub = lane >> 3, li = lane & 7;
    unsigned rowA = blockIdx.x * 64u + warp * 8u + sub;   // < 524288
    const ulonglong2* rpA = (const ulonglong2*)(bias + (size_t)rowA * DB);
    const ulonglong2* rpB = (const ulonglong2*)(bias + (size_t)(rowA + 4u) * DB);

    unsigned long long xa[8], xb[8];
#pragma unroll
    for (int j = 0; j < 4; j++) {
        ulonglong2 t = rpA[j*8 + li];
        xa[2*j] = t.x; xa[2*j+1] = t.y;
    }
#pragma unroll
    for (int j = 0; j < 4; j++) {
        ulonglong2 t = rpB[j*8 + li];
        xb[2*j] = t.x; xb[2*j+1] = t.y;
    }

    // stats (packed), both rows
    unsigned long long s1a = xa[0], s2a = 0ull;
    unsigned long long s1b = xb[0], s2b = 0ull;
    ffma2(s2a, xa[0], xa[0]);
    ffma2(s2b, xb[0], xb[0]);
#pragma unroll
    for (int j = 1; j < 8; j++) {
        fadd2(s1a, xa[j]); ffma2(s2a, xa[j], xa[j]);
        fadd2(s1b, xb[j]); ffma2(s2b, xb[j], xb[j]);
    }

    // 8 head-dots, both rows; each weight LDS serves 4 FFMA2 (2 per row)
    const ulonglong2* wsp = (const ulonglong2*)swg;  // index: h*32 + j*8 + li
    float dA[NH], dB[NH];
#pragma unroll
    for (int h = 0; h < NH; h++) {
        unsigned long long aA = 0ull, aB = 0ull;
#pragma unroll
        for (int j = 0; j < 4; j++) {
            ulonglong2 w = wsp[h*32 + j*8 + li];
            ffma2(aA, xa[2*j],   w.x);
            ffma2(aA, xa[2*j+1], w.y);
            ffma2(aB, xb[2*j],   w.x);
            ffma2(aB, xb[2*j+1], w.y);
        }
        float2 u;
        u = unpack2(aA); dA[h] = u.x + u.y;
        u = unpack2(aB); dB[h] = u.x + u.y;
    }

    float2 t;
    t = unpack2(s1a); float sa1 = t.x + t.y;
    t = unpack2(s2a); float sa2 = t.x + t.y;
    t = unpack2(s1b); float sb1 = t.x + t.y;
    t = unpack2(s2b); float sb2 = t.x + t.y;

    // reduce across the 8 lanes of each row (offsets 1,2,4 stay within li-group)
#pragma unroll
    for (int off = 4; off; off >>= 1) {
        sa1 += __shfl_xor_sync(0xffffffffu, sa1, off);
        sa2 += __shfl_xor_sync(0xffffffffu, sa2, off);
        sb1 += __shfl_xor_sync(0xffffffffu, sb1, off);
        sb2 += __shfl_xor_sync(0xffffffffu, sb2, off);
#pragma unroll
        for (int h = 0; h < NH; h++) {
            dA[h] += __shfl_xor_sync(0xffffffffu, dA[h], off);
            dB[h] += __shfl_xor_sync(0xffffffffu, dB[h], off);
        }
    }

    float muA = sa1 * (1.f/128.f);
    float vaA = fmaf(sa2, 1.f/128.f, -muA*muA);
    float rsA = rsqrtf(vaA + 1e-5f);
    float muB = sb1 * (1.f/128.f);
    float vaB = fmaf(sb2, 1.f/128.f, -muB*muB);
    float rsB = rsqrtf(vaB + 1e-5f);

    // lane li takes head li for both its rows
    float dhA = dA[0], dhB = dB[0];
#pragma unroll
    for (int h = 1; h < NH; h++) {
        dhA = (li == h) ? dA[h] : dhA;
        dhB = (li == h) ? dB[h] : dhB;
    }
    float valA = fmaf(rsA, dhA - muA*scw[li], sbb[li]);
    float valB = fmaf(rsB, dhB - muB*scw[li], sbb[li]);

    sval[warp*72 + li*9 + sub]     = valA;
    sval[warp*72 + li*9 + sub + 4] = valB;
    __syncthreads();

    // coalesced emit: all 64 rows of this block share (bq, q); k-run of 64
    unsigned rblk = blockIdx.x * 64u;
    unsigned bq = rblk >> 18;
    unsigned q  = (rblk >> 9) & 511u;
    unsigned k0 = rblk & 511u;
    int h  = tid >> 5;
    int kk = tid & 31;
    float* outp = g_pb + ((size_t)(bq*NH + h)*LSEQ + q)*LSEQ + k0;
    outp[kk]      = sval[(kk >> 3)*72      + h*9 + (kk & 7)];
    outp[kk + 32] = sval[((kk+32) >> 3)*72 + h*9 + (kk & 7)];
}

// ---------------- flash-style attention + gate ----------------
// block: 128 threads, 16 q rows; thread = (ty 0..15: 1 q row, tx 0..7)
// Ps stride padded to 68 (the stride-64 version is a 16-way LDS conflict).
__global__ void __launch_bounds__(128) attn_kernel() {
    __shared__ __align__(16) float Qs[16*36];
    __shared__ __align__(16) float Ks[64*36];
    __shared__ __align__(16) float Vs[64*32];
    __shared__ __align__(16) float Ps[16*68];
    int tid = threadIdx.x;
    int bh = blockIdx.x >> 5;              // 512 blocks = 16 bh * 32 q-tiles
    int q0 = (blockIdx.x & 31) * 16;
    const float* Qg = g_q + (size_t)bh * LSEQ * HD;
    const float* Kg = g_k + (size_t)bh * LSEQ * HD;
    const float* Vg = g_v + (size_t)bh * LSEQ * HD;
    {
        int r = tid >> 3, c = tid & 7;
        *(float4*)&Qs[r*36 + c*4] = *(const float4*)(Qg + (size_t)(q0+r)*HD + c*4);
    }
    int ty = tid >> 3, tx = tid & 7;
    const float* pb = g_pb + ((size_t)bh * LSEQ + q0 + ty) * LSEQ;
    float m = __int_as_float(0xff800000u);
    float lsum = 0.f;
    float acc[4] = {0,0,0,0};

    for (int kt = 0; kt < LSEQ; kt += 64) {
        __syncthreads();
        for (int i = tid; i < 512; i += 128) {
            int r = i >> 3, c = i & 7;
            *(float4*)&Ks[r*36 + c*4] = *(const float4*)(Kg + (size_t)(kt+r)*HD + c*4);
        }
        for (int i = tid; i < 512; i += 128) {
            int r = i >> 3, c = i & 7;
            *(float4*)&Vs[r*32 + c*4] = *(const float4*)(Vg + (size_t)(kt+r)*HD + c*4);
        }
        __syncthreads();
        float sv[8];
#pragma unroll
        for (int j = 0; j < 8; j++) sv[j] = pb[kt + tx + 8*j];
#pragma unroll
        for (int d4 = 0; d4 < 8; d4++) {
            float4 a = *(float4*)&Qs[ty*36 + d4*4];
#pragma unroll
            for (int j = 0; j < 8; j++) {
                float4 kv = *(float4*)&Ks[(tx + 8*j)*36 + d4*4];
                sv[j] = fmaf(a.x,kv.x, fmaf(a.y,kv.y, fmaf(a.z,kv.z, fmaf(a.w,kv.w, sv[j]))));
            }
        }
        float mx = sv[0];
#pragma unroll
        for (int j = 1; j < 8; j++) mx = fmaxf(mx, sv[j]);
#pragma unroll
        for (int off = 4; off; off >>= 1)
            mx = fmaxf(mx, __shfl_xor_sync(0xffffffffu, mx, off));
        float mn = fmaxf(m, mx);
        float sc = __expf(m - mn);
        float sum = 0.f;
#pragma unroll
        for (int j = 0; j < 8; j++) { sv[j] = __expf(sv[j] - mn); sum += sv[j]; }
#pragma unroll
        for (int off = 4; off; off >>= 1)
            sum += __shfl_xor_sync(0xffffffffu, sum, off);
        lsum = lsum*sc + sum;
        m = mn;
#pragma unroll
        for (int j = 0; j < 4; j++) acc[j] *= sc;
#pragma unroll
        for (int j = 0; j < 8; j++) Ps[ty*68 + tx + 8*j] = sv[j];
        __syncthreads();
#pragma unroll
        for (int k4 = 0; k4 < 16; k4++) {
            float4 pa = *(float4*)&Ps[ty*68 + k4*4];
            float4 va = *(float4*)&Vs[(k4*4+0)*32 + tx*4];
            float4 vb = *(float4*)&Vs[(k4*4+1)*32 + tx*4];
            float4 vc = *(float4*)&Vs[(k4*4+2)*32 + tx*4];
            float4 vd = *(float4*)&Vs[(k4*4+3)*32 + tx*4];
            acc[0]=fmaf(pa.x,va.x,acc[0]); acc[1]=fmaf(pa.x,va.y,acc[1]); acc[2]=fmaf(pa.x,va.z,acc[2]); acc[3]=fmaf(pa.x,va.w,acc[3]);
            acc[0]=fmaf(pa.y,vb.x,acc[0]); acc[1]=fmaf(pa.y,vb.y,acc[1]); acc[2]=fmaf(pa.y,vb.z,acc[2]); acc[3]=fmaf(pa.y,vb.w,acc[3]);
            acc[0]=fmaf(pa.z,vc.x,acc[0]); acc[1]=fmaf(pa.z,vc.y,acc[1]); acc[2]=fmaf(pa.z,vc.z,acc[2]); acc[3]=fmaf(pa.z,vc.w,acc[3]);
            acc[0]=fmaf(pa.w,vd.x,acc[0]); acc[1]=fmaf(pa.w,vd.y,acc[1]); acc[2]=fmaf(pa.w,vd.z,acc[2]); acc[3]=fmaf(pa.w,vd.w,acc[3]);
        }
    }
    float inv = 1.f / lsum;
    int b = bh >> 3, h = bh & 7;
    int mrow = b * LSEQ + q0 + ty;
    float4 g = *(const float4*)(g_gate + (size_t)mrow * DG + h*HD + tx*4);
    float4 o = make_float4(acc[0]*inv*g.x, acc[1]*inv*g.y, acc[2]*inv*g.z, acc[3]*inv*g.w);
    *(float4*)(g_hid + (size_t)mrow*DG + h*HD + tx*4) = o;
}

// ---------------- final GEMM: hid @ Wout + bout ----------------
__global__ void __launch_bounds__(256) gemm_out(const float* __restrict__ Wout,
                                                const float* __restrict__ bout,
                                                float* __restrict__ out) {
    __shared__ __align__(16) float Ast[16*68];
    __shared__ __align__(16) float Bs [16*68];
    int tid = threadIdx.x;
    int bm = blockIdx.y * 64;
    int bn = blockIdx.x * 64;
    int ty = tid >> 4, tx = tid & 15;
    int ar = tid >> 2, ac4 = tid & 3;
    int br = tid >> 4, bc4 = tid & 15;
    float acc[4][4] = {};
    for (int kb = 0; kb < 256; kb += 16) {
        float4 av = *(const float4*)(g_hid + (size_t)(bm+ar)*256 + kb + ac4*4);
        Ast[(ac4*4+0)*68 + ar] = av.x;
        Ast[(ac4*4+1)*68 + ar] = av.y;
        Ast[(ac4*4+2)*68 + ar] = av.z;
        Ast[(ac4*4+3)*68 + ar] = av.w;
        *(float4*)&Bs[br*68 + bc4*4] = *(const float4*)(Wout + (size_t)(kb+br)*256 + bn + bc4*4);
        __syncthreads();
#pragma unroll
        for (int k = 0; k < 16; k++) {
            float4 a = *(float4*)&Ast[k*68 + ty*4];
            float4 b = *(float4*)&Bs [k*68 + tx*4];
            acc[0][0]=fmaf(a.x,b.x,acc[0][0]); acc[0][1]=fmaf(a.x,b.y,acc[0][1]);
            acc[0][2]=fmaf(a.x,b.z,acc[0][2]); acc[0][3]=fmaf(a.x,b.w,acc[0][3]);
            acc[1][0]=fmaf(a.y,b.x,acc[1][0]); acc[1][1]=fmaf(a.y,b.y,acc[1][1]);
            acc[1][2]=fmaf(a.y,b.z,acc[1][2]); acc[1][3]=fmaf(a.y,b.w,acc[1][3]);
            acc[2][0]=fmaf(a.z,b.x,acc[2][0]); acc[2][1]=fmaf(a.z,b.y,acc[2][1]);
            acc[2][2]=fmaf(a.z,b.z,acc[2][2]); acc[2][3]=fmaf(a.z,b.w,acc[2][3]);
            acc[3][0]=fmaf(a.w,b.x,acc[3][0]); acc[3][1]=fmaf(a.w,b.y,acc[3][1]);
            acc[3][2]=fmaf(a.w,b.z,acc[3][2]); acc[3][3]=fmaf(a.w,b.w,acc[3][3]);
        }
        __syncthreads();
    }
#pragma unroll
    for (int i = 0; i < 4; i++) {
#pragma unroll
        for (int j = 0; j < 4; j++) {
            int m = bm + ty*4 + i;
            int n = bn + tx*4 + j;
            out[(size_t)m*256 + n] = acc[i][j] + bout[n];
        }
    }
}

// ---------------- launch ----------------
extern "C" void kernel_launch(void* const* d_in, const int* in_sizes, int n_in,
                              void* d_out, int out_size) {
    const float* x       = (const float*)d_in[0];
    const float* bias    = (const float*)d_in[1];
    const float* g_gamma = (const float*)d_in[2];
    const float* g_beta  = (const float*)d_in[3];
    const float* b_gamma = (const float*)d_in[4];
    const float* b_beta  = (const float*)d_in[5];
    const float* Wq      = (const float*)d_in[6];
    const float* Wk      = (const float*)d_in[7];
    const float* Wv      = (const float*)d_in[8];
    const float* Wb      = (const float*)d_in[9];
    const float* Wg      = (const float*)d_in[10];
    const float* bg      = (const float*)d_in[11];
    const float* Wout    = (const float*)d_in[12];
    const float* bout    = (const float*)d_in[13];
    float* out = (float*)d_out;

    prep_wb<<<1, 128>>>(b_gamma, b_beta, Wb);
    ln_x<<<256, 128>>>(x, g_gamma, g_beta);
    gemm_qkvg<<<dim3(16, 16), 256>>>(Wq, Wk, Wv, Wg, bg);
    pair_ln<<<8192, 256>>>(bias);
    attn_kernel<<<512, 128>>>();
    gemm_out<<<dim3(4, 16), 256>>>(Wout, bout, out);
}

// round 8
// speedup vs baseline: 1.2256x; 1.0610x over previous
#include <cuda_runtime.h>
#include <math.h>

#define LSEQ 512
#define BATCH 2
#define DG 256
#define DB 128
#define NH 8
#define HD 32
#define BH (BATCH*NH)   // 16

// ---------------- scratch (device globals; no allocation allowed) ----------------
__device__ float g_xn[BATCH*LSEQ*DG];        // LN(x)                [1024][256]
__device__ float g_q[BH*LSEQ*HD];            // [b*h][l][32]
__device__ float g_k[BH*LSEQ*HD];            // pre-scaled by 1/sqrt(32)
__device__ float g_v[BH*LSEQ*HD];
__device__ float g_gate[BATCH*LSEQ*DG];      // sigmoid(xn@Wg+bg)    [1024][256]
__device__ float g_pb[(size_t)BH*LSEQ*LSEQ]; // pair bias            [b*h][q][k]
__device__ float g_hid[BATCH*LSEQ*DG];       // gate * attn_out      [1024][256]
__device__ float g_wgt[NH*DB];               // b_gamma[i]*Wb[i][h]  [h][i]
__device__ float g_cw[NH];                   // sum_i b_gamma[i]*Wb[i][h]
__device__ float g_bb[NH];                   // b_beta @ Wb[:,h]

// packed f32x2 helpers (sm_10x FFMA2 path — PTX only)
__device__ __forceinline__ void ffma2(unsigned long long& acc,
                                      unsigned long long a,
                                      unsigned long long b) {
    asm("fma.rn.f32x2 %0, %1, %2, %0;" : "+l"(acc) : "l"(a), "l"(b));
}
__device__ __forceinline__ void fadd2(unsigned long long& acc, unsigned long long a) {
    asm("add.rn.f32x2 %0, %1, %0;" : "+l"(acc) : "l"(a));
}
__device__ __forceinline__ float2 unpack2(unsigned long long v) {
    float2 r;
    asm("mov.b64 {%0, %1}, %2;" : "=f"(r.x), "=f"(r.y) : "l"(v));
    return r;
}

// ---------------- prep: fold b_gamma/b_beta into Wb ----------------
__global__ void prep_wb(const float* __restrict__ b_gamma,
                        const float* __restrict__ b_beta,
                        const float* __restrict__ Wb) {
    __shared__ float sc[NH][DB];
    __shared__ float sb[NH][DB];
    int i = threadIdx.x;            // 128 threads
    float g = b_gamma[i];
    float bt = b_beta[i];
#pragma unroll
    for (int h = 0; h < NH; h++) {
        float w = Wb[i*NH + h];
        g_wgt[h*DB + i] = g * w;
        sc[h][i] = g * w;
        sb[h][i] = bt * w;
    }
    __syncthreads();
    if (i < NH) {
        float a = 0.f, b2 = 0.f;
        for (int j = 0; j < DB; j++) { a += sc[i][j]; b2 += sb[i][j]; }
        g_cw[i] = a;
        g_bb[i] = b2;
    }
}

// ---------------- LN over x rows (dim 256), warp per row ----------------
__global__ void __launch_bounds__(128) ln_x(const float* __restrict__ x,
                                            const float* __restrict__ gamma,
                                            const float* __restrict__ beta) {
    int warp = threadIdx.x >> 5, lane = threadIdx.x & 31;
    int row = blockIdx.x * 4 + warp;           // 1024 rows, grid 256
    const float* rp = x + (size_t)row * DG;
    float4 v0 = *(const float4*)(rp + lane*4);
    float4 v1 = *(const float4*)(rp + 128 + lane*4);
    float s1 = v0.x+v0.y+v0.z+v0.w + v1.x+v1.y+v1.z+v1.w;
    float s2 = v0.x*v0.x+v0.y*v0.y+v0.z*v0.z+v0.w*v0.w
             + v1.x*v1.x+v1.y*v1.y+v1.z*v1.z+v1.w*v1.w;
#pragma unroll
    for (int off = 16; off; off >>= 1) {
        s1 += __shfl_xor_sync(0xffffffffu, s1, off);
        s2 += __shfl_xor_sync(0xffffffffu, s2, off);
    }
    float mu = s1 * (1.f/256.f);
    float var = s2 * (1.f/256.f) - mu*mu;
    float rstd = rsqrtf(var + 1e-5f);
    float4 gm0 = *(const float4*)(gamma + lane*4);
    float4 gm1 = *(const float4*)(gamma + 128 + lane*4);
    float4 bt0 = *(const float4*)(beta + lane*4);
    float4 bt1 = *(const float4*)(beta + 128 + lane*4);
    float4 o0, o1;
    o0.x = (v0.x-mu)*rstd*gm0.x + bt0.x; o0.y = (v0.y-mu)*rstd*gm0.y + bt0.y;
    o0.z = (v0.z-mu)*rstd*gm0.z + bt0.z; o0.w = (v0.w-mu)*rstd*gm0.w + bt0.w;
    o1.x = (v1.x-mu)*rstd*gm1.x + bt1.x; o1.y = (v1.y-mu)*rstd*gm1.y + bt1.y;
    o1.z = (v1.z-mu)*rstd*gm1.z + bt1.z; o1.w = (v1.w-mu)*rstd*gm1.w + bt1.w;
    *(float4*)(g_xn + (size_t)row*DG + lane*4) = o0;
    *(float4*)(g_xn + (size_t)row*DG + 128 + lane*4) = o1;
}

// ---------------- fused GEMM: xn @ [Wq|Wk|Wv|Wg] (M=1024, N=1024, K=256) ----------------
__global__ void __launch_bounds__(256) gemm_qkvg(const float* __restrict__ Wq,
                                                 const float* __restrict__ Wk,
                                                 const float* __restrict__ Wv,
                                                 const float* __restrict__ Wg,
                                                 const float* __restrict__ bg) {
    __shared__ __align__(16) float Ast[16*68];   // [k][m] transposed, padded
    __shared__ __align__(16) float Bs [16*68];   // [k][n], padded
    int tid = threadIdx.x;
    int bm = blockIdx.y * 64;
    int bn_g = blockIdx.x * 64;          // 0..1023
    int which = bn_g >> 8;               // 0:Q 1:K 2:V 3:G
    int bn = bn_g & 255;
    const float* W = (which==0) ? Wq : (which==1) ? Wk : (which==2) ? Wv : Wg;
    int ty = tid >> 4, tx = tid & 15;
    int ar = tid >> 2, ac4 = tid & 3;
    int br = tid >> 4, bc4 = tid & 15;
    float acc[4][4] = {};
    for (int kb = 0; kb < 256; kb += 16) {
        float4 av = *(const float4*)(g_xn + (size_t)(bm+ar)*256 + kb + ac4*4);
        Ast[(ac4*4+0)*68 + ar] = av.x;
        Ast[(ac4*4+1)*68 + ar] = av.y;
        Ast[(ac4*4+2)*68 + ar] = av.z;
        Ast[(ac4*4+3)*68 + ar] = av.w;
        *(float4*)&Bs[br*68 + bc4*4] = *(const float4*)(W + (size_t)(kb+br)*256 + bn + bc4*4);
        __syncthreads();
#pragma unroll
        for (int k = 0; k < 16; k++) {
            float4 a = *(float4*)&Ast[k*68 + ty*4];
            float4 b = *(float4*)&Bs [k*68 + tx*4];
            acc[0][0]=fmaf(a.x,b.x,acc[0][0]); acc[0][1]=fmaf(a.x,b.y,acc[0][1]);
            acc[0][2]=fmaf(a.x,b.z,acc[0][2]); acc[0][3]=fmaf(a.x,b.w,acc[0][3]);
            acc[1][0]=fmaf(a.y,b.x,acc[1][0]); acc[1][1]=fmaf(a.y,b.y,acc[1][1]);
            acc[1][2]=fmaf(a.y,b.z,acc[1][2]); acc[1][3]=fmaf(a.y,b.w,acc[1][3]);
            acc[2][0]=fmaf(a.z,b.x,acc[2][0]); acc[2][1]=fmaf(a.z,b.y,acc[2][1]);
            acc[2][2]=fmaf(a.z,b.z,acc[2][2]); acc[2][3]=fmaf(a.z,b.w,acc[2][3]);
            acc[3][0]=fmaf(a.w,b.x,acc[3][0]); acc[3][1]=fmaf(a.w,b.y,acc[3][1]);
            acc[3][2]=fmaf(a.w,b.z,acc[3][2]); acc[3][3]=fmaf(a.w,b.w,acc[3][3]);
        }
        __syncthreads();
    }
    const float kscale = 0.17677669529663687f; // 1/sqrt(32)
#pragma unroll
    for (int i = 0; i < 4; i++) {
#pragma unroll
        for (int j = 0; j < 4; j++) {
            int m = bm + ty*4 + i;
            int n = bn + tx*4 + j;
            float v = acc[i][j];
            if (which < 3) {
                if (which == 1) v *= kscale;
                int b = m >> 9, pos = m & 511, h = n >> 5, d = n & 31;
                float* dst = (which==0) ? g_q : (which==1) ? g_k : g_v;
                dst[((size_t)(b*NH + h)*LSEQ + pos)*HD + d] = v;
            } else {
                v = 1.f / (1.f + __expf(-(v + bg[n])));
                g_gate[(size_t)m*DG + n] = v;
            }
        }
    }
}

// ---------------- fused LN(bias) @ Wb -> pair bias in [b,h,q,k] ----------------
// Warp = 8 rows (sub -> rows base+sub, base+sub+4), lane li owns contiguous 16B
// chunks. Weight LDS.128 feeds FFMA2 for two rows. Head-dots reduced EAGERLY in
// head-pairs with a pairing butterfly (off=1 swaps heads across odd/even lanes)
// -> no dA[8]/dB[8] register arrays, 24 dot-shuffles instead of 48, regs <= 64
// so occupancy doubles vs R6 (that 84-reg/23.5%-occ version was latency-bound).
__global__ void __launch_bounds__(256, 4) pair_ln(const float* __restrict__ bias) {
    __shared__ __align__(16) float swg[NH*DB];
    __shared__ float scw[NH], sbb[NH];
    __shared__ float sval[8*72];    // [warp][head*9 + subrow(0..7)]
    int tid = threadIdx.x;
    for (int i = tid; i < NH*DB; i += 256) swg[i] = g_wgt[i];
    if (tid < NH) { scw[tid] = g_cw[tid]; sbb[tid] = g_bb[tid]; }
    __syncthreads();
    int warp = tid >> 5, lane = tid & 31;
    int sub = lane >> 3, li = lane & 7;
    int b0 = li & 1;
    unsigned rowA = blockIdx.x * 64u + warp * 8u + sub;   // < 524288
    const ulonglong2* rpA = (const ulonglong2*)(bias + (size_t)rowA * DB);
    const ulonglong2* rpB = (const ulonglong2*)(bias + (size_t)(rowA + 4u) * DB);

    unsigned long long xa[8], xb[8];
#pragma unroll
    for (int j = 0; j < 4; j++) {
        ulonglong2 t = rpA[j*8 + li];
        xa[2*j] = t.x; xa[2*j+1] = t.y;
    }
#pragma unroll
    for (int j = 0; j < 4; j++) {
        ulonglong2 t = rpB[j*8 + li];
        xb[2*j] = t.x; xb[2*j+1] = t.y;
    }

    // stats (packed), both rows
    unsigned long long s1a = xa[0], s2a = 0ull;
    unsigned long long s1b = xb[0], s2b = 0ull;
    ffma2(s2a, xa[0], xa[0]);
    ffma2(s2b, xb[0], xb[0]);
#pragma unroll
    for (int j = 1; j < 8; j++) {
        fadd2(s1a, xa[j]); ffma2(s2a, xa[j], xa[j]);
        fadd2(s1b, xb[j]); ffma2(s2b, xb[j], xb[j]);
    }
    float2 t;
    t = unpack2(s1a); float sa1 = t.x + t.y;
    t = unpack2(s2a); float sa2 = t.x + t.y;
    t = unpack2(s1b); float sb1 = t.x + t.y;
    t = unpack2(s2b); float sb2 = t.x + t.y;
#pragma unroll
    for (int off = 4; off; off >>= 1) {
        sa1 += __shfl_xor_sync(0xffffffffu, sa1, off);
        sa2 += __shfl_xor_sync(0xffffffffu, sa2, off);
        sb1 += __shfl_xor_sync(0xffffffffu, sb1, off);
        sb2 += __shfl_xor_sync(0xffffffffu, sb2, off);
    }
    float muA = sa1 * (1.f/128.f);
    float rsA = rsqrtf(fmaf(sa2, 1.f/128.f, -muA*muA) + 1e-5f);
    float muB = sb1 * (1.f/128.f);
    float rsB = rsqrtf(fmaf(sb2, 1.f/128.f, -muB*muB) + 1e-5f);

    // head-pair dots with eager pairing reduction; lane li ends with head li
    const ulonglong2* wsp = (const ulonglong2*)swg;  // index: h*32 + j*8 + li
    float dhA = 0.f, dhB = 0.f;
#pragma unroll
    for (int p = 0; p < 4; p++) {
        unsigned long long aA0 = 0ull, aA1 = 0ull, aB0 = 0ull, aB1 = 0ull;
#pragma unroll
        for (int j = 0; j < 4; j++) {
            ulonglong2 w0 = wsp[(2*p  )*32 + j*8 + li];
            ulonglong2 w1 = wsp[(2*p+1)*32 + j*8 + li];
            ffma2(aA0, xa[2*j],   w0.x); ffma2(aA0, xa[2*j+1], w0.y);
            ffma2(aA1, xa[2*j],   w1.x); ffma2(aA1, xa[2*j+1], w1.y);
            ffma2(aB0, xb[2*j],   w0.x); ffma2(aB0, xb[2*j+1], w0.y);
            ffma2(aB1, xb[2*j],   w1.x); ffma2(aB1, xb[2*j+1], w1.y);
        }
        float2 u;
        u = unpack2(aA0); float fA0 = u.x + u.y;
        u = unpack2(aA1); float fA1 = u.x + u.y;
        u = unpack2(aB0); float fB0 = u.x + u.y;
        u = unpack2(aB1); float fB1 = u.x + u.y;
        // pairing round: even lanes keep head 2p, odd keep 2p+1
        float sA = b0 ? fA0 : fA1;
        float rA = (b0 ? fA1 : fA0) + __shfl_xor_sync(0xffffffffu, sA, 1);
        rA += __shfl_xor_sync(0xffffffffu, rA, 2);
        rA += __shfl_xor_sync(0xffffffffu, rA, 4);
        float sB = b0 ? fB0 : fB1;
        float rB = (b0 ? fB1 : fB0) + __shfl_xor_sync(0xffffffffu, sB, 1);
        rB += __shfl_xor_sync(0xffffffffu, rB, 2);
        rB += __shfl_xor_sync(0xffffffffu, rB, 4);
        if ((li >> 1) == p) { dhA = rA; dhB = rB; }
    }

    float valA = fmaf(rsA, dhA - muA*scw[li], sbb[li]);
    float valB = fmaf(rsB, dhB - muB*scw[li], sbb[li]);

    sval[warp*72 + li*9 + sub]     = valA;
    sval[warp*72 + li*9 + sub + 4] = valB;
    __syncthreads();

    // coalesced emit: all 64 rows of this block share (bq, q); k-run of 64
    unsigned rblk = blockIdx.x * 64u;
    unsigned bq = rblk >> 18;
    unsigned q  = (rblk >> 9) & 511u;
    unsigned k0 = rblk & 511u;
    int h  = tid >> 5;
    int kk = tid & 31;
    float* outp = g_pb + ((size_t)(bq*NH + h)*LSEQ + q)*LSEQ + k0;
    outp[kk]      = sval[(kk >> 3)*72      + h*9 + (kk & 7)];
    outp[kk + 32] = sval[((kk+32) >> 3)*72 + h*9 + (kk & 7)];
}

// ---------------- flash-style attention + gate ----------------
// block: 128 threads, 32 q rows; thread = (ty 0..15: 2 q rows, tx 0..7)
// Ps stride 68: within a warp the 4 ty-rows land at bank slots {0,32,64,96}
// -> conflict-free (stride 64 would alias all rows to slot 0 = 4-way).
__global__ void __launch_bounds__(128) attn_kernel() {
    __shared__ __align__(16) float Qs[32*36];
    __shared__ __align__(16) float Ks[64*36];
    __shared__ __align__(16) float Vs[64*32];
    __shared__ __align__(16) float Ps[32*68];
    int tid = threadIdx.x;
    int bh = blockIdx.x >> 4;
    int q0 = (blockIdx.x & 15) * 32;
    const float* Qg = g_q + (size_t)bh * LSEQ * HD;
    const float* Kg = g_k + (size_t)bh * LSEQ * HD;
    const float* Vg = g_v + (size_t)bh * LSEQ * HD;
    for (int i = tid; i < 256; i += 128) {
        int r = i >> 3, c = i & 7;
        *(float4*)&Qs[r*36 + c*4] = *(const float4*)(Qg + (size_t)(q0+r)*HD + c*4);
    }
    int ty = tid >> 3, tx = tid & 7;
    int qa = q0 + 2*ty;
    const float* pb0 = g_pb + ((size_t)bh * LSEQ + qa) * LSEQ;
    const float* pb1 = pb0 + LSEQ;
    float m0 = __int_as_float(0xff800000u), m1 = m0;
    float l0 = 0.f, l1 = 0.f;
    float c0[4] = {0,0,0,0}, c1[4] = {0,0,0,0};

    for (int kt = 0; kt < LSEQ; kt += 64) {
        __syncthreads();
        for (int i = tid; i < 512; i += 128) {
            int r = i >> 3, c = i & 7;
            *(float4*)&Ks[r*36 + c*4] = *(const float4*)(Kg + (size_t)(kt+r)*HD + c*4);
        }
        for (int i = tid; i < 512; i += 128) {
            int r = i >> 3, c = i & 7;
            *(float4*)&Vs[r*32 + c*4] = *(const float4*)(Vg + (size_t)(kt+r)*HD + c*4);
        }
        __syncthreads();
        float s0[8], s1v[8];
#pragma unroll
        for (int j = 0; j < 8; j++) {
            s0[j]  = pb0[kt + tx + 8*j];
            s1v[j] = pb1[kt + tx + 8*j];
        }
#pragma unroll
        for (int d4 = 0; d4 < 8; d4++) {
            float4 a0 = *(float4*)&Qs[(2*ty  )*36 + d4*4];
            float4 a1 = *(float4*)&Qs[(2*ty+1)*36 + d4*4];
#pragma unroll
            for (int j = 0; j < 8; j++) {
                float4 kv = *(float4*)&Ks[(tx + 8*j)*36 + d4*4];
                s0[j]  = fmaf(a0.x,kv.x, fmaf(a0.y,kv.y, fmaf(a0.z,kv.z, fmaf(a0.w,kv.w, s0[j]))));
                s1v[j] = fmaf(a1.x,kv.x, fmaf(a1.y,kv.y, fmaf(a1.z,kv.z, fmaf(a1.w,kv.w, s1v[j]))));
            }
        }
        float mx0 = s0[0], mx1 = s1v[0];
#pragma unroll
        for (int j = 1; j < 8; j++) { mx0 = fmaxf(mx0, s0[j]); mx1 = fmaxf(mx1, s1v[j]); }
#pragma unroll
        for (int off = 4; off; off >>= 1) {
            mx0 = fmaxf(mx0, __shfl_xor_sync(0xffffffffu, mx0, off));
            mx1 = fmaxf(mx1, __shfl_xor_sync(0xffffffffu, mx1, off));
        }
        float mn0 = fmaxf(m0, mx0), mn1 = fmaxf(m1, mx1);
        float sc0 = __expf(m0 - mn0), sc1 = __expf(m1 - mn1);
        float sum0 = 0.f, sum1 = 0.f;
#pragma unroll
        for (int j = 0; j < 8; j++) {
            s0[j]  = __expf(s0[j]  - mn0); sum0 += s0[j];
            s1v[j] = __expf(s1v[j] - mn1); sum1 += s1v[j];
        }
#pragma unroll
        for (int off = 4; off; off >>= 1) {
            sum0 += __shfl_xor_sync(0xffffffffu, sum0, off);
            sum1 += __shfl_xor_sync(0xffffffffu, sum1, off);
        }
        l0 = l0*sc0 + sum0; l1 = l1*sc1 + sum1;
        m0 = mn0; m1 = mn1;
#pragma unroll
        for (int j = 0; j < 4; j++) { c0[j] *= sc0; c1[j] *= sc1; }
#pragma unroll
        for (int j = 0; j < 8; j++) {
            Ps[(2*ty  )*68 + tx + 8*j] = s0[j];
            Ps[(2*ty+1)*68 + tx + 8*j] = s1v[j];
        }
        __syncthreads();
#pragma unroll
        for (int k4 = 0; k4 < 16; k4++) {
            float4 pa  = *(float4*)&Ps[(2*ty  )*68 + k4*4];
            float4 pbv = *(float4*)&Ps[(2*ty+1)*68 + k4*4];
            float4 va = *(float4*)&Vs[(k4*4+0)*32 + tx*4];
            float4 vb = *(float4*)&Vs[(k4*4+1)*32 + tx*4];
            float4 vc = *(float4*)&Vs[(k4*4+2)*32 + tx*4];
            float4 vd = *(float4*)&Vs[(k4*4+3)*32 + tx*4];
            c0[0]=fmaf(pa.x,va.x,c0[0]); c0[1]=fmaf(pa.x,va.y,c0[1]); c0[2]=fmaf(pa.x,va.z,c0[2]); c0[3]=fmaf(pa.x,va.w,c0[3]);
            c1[0]=fmaf(pbv.x,va.x,c1[0]); c1[1]=fmaf(pbv.x,va.y,c1[1]); c1[2]=fmaf(pbv.x,va.z,c1[2]); c1[3]=fmaf(pbv.x,va.w,c1[3]);
            c0[0]=fmaf(pa.y,vb.x,c0[0]); c0[1]=fmaf(pa.y,vb.y,c0[1]); c0[2]=fmaf(pa.y,vb.z,c0[2]); c0[3]=fmaf(pa.y,vb.w,c0[3]);
            c1[0]=fmaf(pbv.y,vb.x,c1[0]); c1[1]=fmaf(pbv.y,vb.y,c1[1]); c1[2]=fmaf(pbv.y,vb.z,c1[2]); c1[3]=fmaf(pbv.y,vb.w,c1[3]);
            c0[0]=fmaf(pa.z,vc.x,c0[0]); c0[1]=fmaf(pa.z,vc.y,c0[1]); c0[2]=fmaf(pa.z,vc.z,c0[2]); c0[3]=fmaf(pa.z,vc.w,c0[3]);
            c1[0]=fmaf(pbv.z,vc.x,c1[0]); c1[1]=fmaf(pbv.z,vc.y,c1[1]); c1[2]=fmaf(pbv.z,vc.z,c1[2]); c1[3]=fmaf(pbv.z,vc.w,c1[3]);
            c0[0]=fmaf(pa.w,vd.x,c0[0]); c0[1]=fmaf(pa.w,vd.y,c0[1]); c0[2]=fmaf(pa.w,vd.z,c0[2]); c0[3]=fmaf(pa.w,vd.w,c0[3]);
            c1[0]=fmaf(pbv.w,vd.x,c1[0]); c1[1]=fmaf(pbv.w,vd.y,c1[1]); c1[2]=fmaf(pbv.w,vd.z,c1[2]); c1[3]=fmaf(pbv.w,vd.w,c1[3]);
        }
    }
    float inv0 = 1.f / l0, inv1 = 1.f / l1;
    int b = bh >> 3, h = bh & 7;
    int mrow = b * LSEQ + qa;
    const float* gt = g_gate + (size_t)mrow * DG + h*HD + tx*4;
    float4 gA = *(const float4*)gt;
    float4 gB = *(const float4*)(gt + DG);
    float4 oA = make_float4(c0[0]*inv0*gA.x, c0[1]*inv0*gA.y, c0[2]*inv0*gA.z, c0[3]*inv0*gA.w);
    float4 oB = make_float4(c1[0]*inv1*gB.x, c1[1]*inv1*gB.y, c1[2]*inv1*gB.z, c1[3]*inv1*gB.w);
    *(float4*)(g_hid + (size_t)mrow*DG + h*HD + tx*4) = oA;
    *(float4*)(g_hid + (size_t)(mrow+1)*DG + h*HD + tx*4) = oB;
}

// ---------------- final GEMM: hid @ Wout + bout ----------------
__global__ void __launch_bounds__(256) gemm_out(const float* __restrict__ Wout,
                                                const float* __restrict__ bout,
                                                float* __restrict__ out) {
    __shared__ __align__(16) float Ast[16*68];
    __shared__ __align__(16) float Bs [16*68];
    int tid = threadIdx.x;
    int bm = blockIdx.y * 64;
    int bn = blockIdx.x * 64;
    int ty = tid >> 4, tx = tid & 15;
    int ar = tid >> 2, ac4 = tid & 3;
    int br = tid >> 4, bc4 = tid & 15;
    float acc[4][4] = {};
    for (int kb = 0; kb < 256; kb += 16) {
        float4 av = *(const float4*)(g_hid + (size_t)(bm+ar)*256 + kb + ac4*4);
        Ast[(ac4*4+0)*68 + ar] = av.x;
        Ast[(ac4*4+1)*68 + ar] = av.y;
        Ast[(ac4*4+2)*68 + ar] = av.z;
        Ast[(ac4*4+3)*68 + ar] = av.w;
        *(float4*)&Bs[br*68 + bc4*4] = *(const float4*)(Wout + (size_t)(kb+br)*256 + bn + bc4*4);
        __syncthreads();
#pragma unroll
        for (int k = 0; k < 16; k++) {
            float4 a = *(float4*)&Ast[k*68 + ty*4];
            float4 b = *(float4*)&Bs [k*68 + tx*4];
            acc[0][0]=fmaf(a.x,b.x,acc[0][0]); acc[0][1]=fmaf(a.x,b.y,acc[0][1]);
            acc[0][2]=fmaf(a.x,b.z,acc[0][2]); acc[0][3]=fmaf(a.x,b.w,acc[0][3]);
            acc[1][0]=fmaf(a.y,b.x,acc[1][0]); acc[1][1]=fmaf(a.y,b.y,acc[1][1]);
            acc[1][2]=fmaf(a.y,b.z,acc[1][2]); acc[1][3]=fmaf(a.y,b.w,acc[1][3]);
            acc[2][0]=fmaf(a.z,b.x,acc[2][0]); acc[2][1]=fmaf(a.z,b.y,acc[2][1]);
            acc[2][2]=fmaf(a.z,b.z,acc[2][2]); acc[2][3]=fmaf(a.z,b.w,acc[2][3]);
            acc[3][0]=fmaf(a.w,b.x,acc[3][0]); acc[3][1]=fmaf(a.w,b.y,acc[3][1]);
            acc[3][2]=fmaf(a.w,b.z,acc[3][2]); acc[3][3]=fmaf(a.w,b.w,acc[3][3]);
        }
        __syncthreads();
    }
#pragma unroll
    for (int i = 0; i < 4; i++) {
#pragma unroll
        for (int j = 0; j < 4; j++) {
            int m = bm + ty*4 + i;
            int n = bn + tx*4 + j;
            out[(size_t)m*256 + n] = acc[i][j] + bout[n];
        }
    }
}

// ---------------- launch ----------------
extern "C" void kernel_launch(void* const* d_in, const int* in_sizes, int n_in,
                              void* d_out, int out_size) {
    const float* x       = (const float*)d_in[0];
    const float* bias    = (const float*)d_in[1];
    const float* g_gamma = (const float*)d_in[2];
    const float* g_beta  = (const float*)d_in[3];
    const float* b_gamma = (const float*)d_in[4];
    const float* b_beta  = (const float*)d_in[5];
    const float* Wq      = (const float*)d_in[6];
    const float* Wk      = (const float*)d_in[7];
    const float* Wv      = (const float*)d_in[8];
    const float* Wb      = (const float*)d_in[9];
    const float* Wg      = (const float*)d_in[10];
    const float* bg      = (const float*)d_in[11];
    const float* Wout    = (const float*)d_in[12];
    const float* bout    = (const float*)d_in[13];
    float* out = (float*)d_out;

    prep_wb<<<1, 128>>>(b_gamma, b_beta, Wb);
    ln_x<<<256, 128>>>(x, g_gamma, g_beta);
    gemm_qkvg<<<dim3(16, 16), 256>>>(Wq, Wk, Wv, Wg, bg);
    pair_ln<<<8192, 256>>>(bias);
    attn_kernel<<<256, 128>>>();
    gemm_out<<<dim3(4, 16), 256>>>(Wout, bout, out);
}

// round 9
// speedup vs baseline: 1.3360x; 1.0901x over previous
#include <cuda_runtime.h>
#include <math.h>

#define LSEQ 512
#define BATCH 2
#define DG 256
#define DB 128
#define NH 8
#define HD 32
#define BH (BATCH*NH)   // 16

// ---------------- scratch (device globals; no allocation allowed) ----------------
__device__ float g_xn[BATCH*LSEQ*DG];        // LN(x)                [1024][256]
__device__ float g_q[BH*LSEQ*HD];            // [b*h][l][32]
__device__ float g_k[BH*LSEQ*HD];            // pre-scaled by 1/sqrt(32)
__device__ float g_v[BH*LSEQ*HD];
__device__ float g_gate[BATCH*LSEQ*DG];      // sigmoid(xn@Wg+bg)    [1024][256]
__device__ float g_pb[(size_t)BH*LSEQ*LSEQ]; // pair bias            [b*h][q][k]
__device__ float g_hid[BATCH*LSEQ*DG];       // gate * attn_out      [1024][256]
__device__ float g_wgt[NH*DB];               // b_gamma[i]*Wb[i][h]  [h][i]
__device__ float g_cw[NH];                   // sum_i b_gamma[i]*Wb[i][h]
__device__ float g_bb[NH];                   // b_beta @ Wb[:,h]

// packed f32x2 helpers (sm_10x FFMA2 path — PTX only)
__device__ __forceinline__ void ffma2(unsigned long long& acc,
                                      unsigned long long a,
                                      unsigned long long b) {
    asm("fma.rn.f32x2 %0, %1, %2, %0;" : "+l"(acc) : "l"(a), "l"(b));
}
__device__ __forceinline__ void fadd2(unsigned long long& acc, unsigned long long a) {
    asm("add.rn.f32x2 %0, %1, %0;" : "+l"(acc) : "l"(a));
}
__device__ __forceinline__ float2 unpack2(unsigned long long v) {
    float2 r;
    asm("mov.b64 {%0, %1}, %2;" : "=f"(r.x), "=f"(r.y) : "l"(v));
    return r;
}

// ============ merged kernel 1: prep_wb (block 0) + ln_x (blocks 1..128) ============
__global__ void __launch_bounds__(256) prep_and_lnx(
        const float* __restrict__ b_gamma, const float* __restrict__ b_beta,
        const float* __restrict__ Wb,
        const float* __restrict__ x, const float* __restrict__ gamma,
        const float* __restrict__ beta) {
    int tid = threadIdx.x;
    if (blockIdx.x == 0) {
        // ---- prep_wb (128 threads) ----
        __shared__ float sc[NH][DB];
        __shared__ float sb[NH][DB];
        if (tid < DB) {
            float g = b_gamma[tid];
            float bt = b_beta[tid];
#pragma unroll
            for (int h = 0; h < NH; h++) {
                float w = Wb[tid*NH + h];
                g_wgt[h*DB + tid] = g * w;
                sc[h][tid] = g * w;
                sb[h][tid] = bt * w;
            }
        }
        __syncthreads();
        if (tid < NH) {
            float a = 0.f, b2 = 0.f;
            for (int j = 0; j < DB; j++) { a += sc[tid][j]; b2 += sb[tid][j]; }
            g_cw[tid] = a;
            g_bb[tid] = b2;
        }
        return;
    }
    // ---- ln_x: 8 warps -> 8 rows per block ----
    int warp = tid >> 5, lane = tid & 31;
    int row = (blockIdx.x - 1) * 8 + warp;     // 1024 rows over 128 blocks
    const float* rp = x + (size_t)row * DG;
    float4 v0 = *(const float4*)(rp + lane*4);
    float4 v1 = *(const float4*)(rp + 128 + lane*4);
    float s1 = v0.x+v0.y+v0.z+v0.w + v1.x+v1.y+v1.z+v1.w;
    float s2 = v0.x*v0.x+v0.y*v0.y+v0.z*v0.z+v0.w*v0.w
             + v1.x*v1.x+v1.y*v1.y+v1.z*v1.z+v1.w*v1.w;
#pragma unroll
    for (int off = 16; off; off >>= 1) {
        s1 += __shfl_xor_sync(0xffffffffu, s1, off);
        s2 += __shfl_xor_sync(0xffffffffu, s2, off);
    }
    float mu = s1 * (1.f/256.f);
    float var = s2 * (1.f/256.f) - mu*mu;
    float rstd = rsqrtf(var + 1e-5f);
    float4 gm0 = *(const float4*)(gamma + lane*4);
    float4 gm1 = *(const float4*)(gamma + 128 + lane*4);
    float4 bt0 = *(const float4*)(beta + lane*4);
    float4 bt1 = *(const float4*)(beta + 128 + lane*4);
    float4 o0, o1;
    o0.x = (v0.x-mu)*rstd*gm0.x + bt0.x; o0.y = (v0.y-mu)*rstd*gm0.y + bt0.y;
    o0.z = (v0.z-mu)*rstd*gm0.z + bt0.z; o0.w = (v0.w-mu)*rstd*gm0.w + bt0.w;
    o1.x = (v1.x-mu)*rstd*gm1.x + bt1.x; o1.y = (v1.y-mu)*rstd*gm1.y + bt1.y;
    o1.z = (v1.z-mu)*rstd*gm1.z + bt1.z; o1.w = (v1.w-mu)*rstd*gm1.w + bt1.w;
    *(float4*)(g_xn + (size_t)row*DG + lane*4) = o0;
    *(float4*)(g_xn + (size_t)row*DG + 128 + lane*4) = o1;
}

// ============ merged kernel 2: gemm_qkvg (blocks 0..255) + pair_ln (256..8447) ====
// gemm blocks first in grid order -> wave-1 schedules them alongside pair_ln
// blocks; the compute-bound gemm hides inside pair_ln's DRAM stalls.
__global__ void __launch_bounds__(256, 4) fused_qkvg_pairln(
        const float* __restrict__ Wq, const float* __restrict__ Wk,
        const float* __restrict__ Wv, const float* __restrict__ Wg,
        const float* __restrict__ bg, const float* __restrict__ bias) {
    __shared__ __align__(16) float smem[2*16*68];   // union for both branches
    int tid = threadIdx.x;

    if (blockIdx.x < 256) {
        // ---------------- gemm_qkvg ----------------
        float* Ast = smem;            // [k][m] transposed, padded 68
        float* Bs  = smem + 16*68;    // [k][n], padded 68
        int id = blockIdx.x;
        int bm = (id >> 4) * 64;
        int bn_g = (id & 15) * 64;           // 0..1023
        int which = bn_g >> 8;               // 0:Q 1:K 2:V 3:G
        int bn = bn_g & 255;
        const float* W = (which==0) ? Wq : (which==1) ? Wk : (which==2) ? Wv : Wg;
        int ty = tid >> 4, tx = tid & 15;
        int ar = tid >> 2, ac4 = tid & 3;
        int br = tid >> 4, bc4 = tid & 15;
        float acc[4][4] = {};
        for (int kb = 0; kb < 256; kb += 16) {
            float4 av = *(const float4*)(g_xn + (size_t)(bm+ar)*256 + kb + ac4*4);
            Ast[(ac4*4+0)*68 + ar] = av.x;
            Ast[(ac4*4+1)*68 + ar] = av.y;
            Ast[(ac4*4+2)*68 + ar] = av.z;
            Ast[(ac4*4+3)*68 + ar] = av.w;
            *(float4*)&Bs[br*68 + bc4*4] = *(const float4*)(W + (size_t)(kb+br)*256 + bn + bc4*4);
            __syncthreads();
#pragma unroll
            for (int k = 0; k < 16; k++) {
                float4 a = *(float4*)&Ast[k*68 + ty*4];
                float4 b = *(float4*)&Bs [k*68 + tx*4];
                acc[0][0]=fmaf(a.x,b.x,acc[0][0]); acc[0][1]=fmaf(a.x,b.y,acc[0][1]);
                acc[0][2]=fmaf(a.x,b.z,acc[0][2]); acc[0][3]=fmaf(a.x,b.w,acc[0][3]);
                acc[1][0]=fmaf(a.y,b.x,acc[1][0]); acc[1][1]=fmaf(a.y,b.y,acc[1][1]);
                acc[1][2]=fmaf(a.y,b.z,acc[1][2]); acc[1][3]=fmaf(a.y,b.w,acc[1][3]);
                acc[2][0]=fmaf(a.z,b.x,acc[2][0]); acc[2][1]=fmaf(a.z,b.y,acc[2][1]);
                acc[2][2]=fmaf(a.z,b.z,acc[2][2]); acc[2][3]=fmaf(a.z,b.w,acc[2][3]);
                acc[3][0]=fmaf(a.w,b.x,acc[3][0]); acc[3][1]=fmaf(a.w,b.y,acc[3][1]);
                acc[3][2]=fmaf(a.w,b.z,acc[3][2]); acc[3][3]=fmaf(a.w,b.w,acc[3][3]);
            }
            __syncthreads();
        }
        const float kscale = 0.17677669529663687f; // 1/sqrt(32)
#pragma unroll
        for (int i = 0; i < 4; i++) {
#pragma unroll
            for (int j = 0; j < 4; j++) {
                int m = bm + ty*4 + i;
                int n = bn + tx*4 + j;
                float v = acc[i][j];
                if (which < 3) {
                    if (which == 1) v *= kscale;
                    int b = m >> 9, pos = m & 511, h = n >> 5, d = n & 31;
                    float* dst = (which==0) ? g_q : (which==1) ? g_k : g_v;
                    dst[((size_t)(b*NH + h)*LSEQ + pos)*HD + d] = v;
                } else {
                    v = 1.f / (1.f + __expf(-(v + bg[n])));
                    g_gate[(size_t)m*DG + n] = v;
                }
            }
        }
        return;
    }

    // ---------------- pair_ln ----------------
    // Warp = 8 rows (sub -> rows base+sub, base+sub+4), lane li owns contiguous
    // 16B chunks. Eager head-pair reduction keeps regs <= 64.
    float* swg = smem;                        // NH*DB = 1024 floats
    float* scw = smem + NH*DB;                // 8
    float* sbb = smem + NH*DB + NH;           // 8
    float* sval = smem + NH*DB + 2*NH;        // 8*72 = 576
    unsigned pbid = blockIdx.x - 256u;
    for (int i = tid; i < NH*DB; i += 256) swg[i] = g_wgt[i];
    if (tid < NH) { scw[tid] = g_cw[tid]; sbb[tid] = g_bb[tid]; }
    __syncthreads();
    int warp = tid >> 5, lane = tid & 31;
    int sub = lane >> 3, li = lane & 7;
    int b0 = li & 1;
    unsigned rowA = pbid * 64u + warp * 8u + sub;   // < 524288
    const ulonglong2* rpA = (const ulonglong2*)(bias + (size_t)rowA * DB);
    const ulonglong2* rpB = (const ulonglong2*)(bias + (size_t)(rowA + 4u) * DB);

    unsigned long long xa[8], xb[8];
#pragma unroll
    for (int j = 0; j < 4; j++) {
        ulonglong2 t = rpA[j*8 + li];
        xa[2*j] = t.x; xa[2*j+1] = t.y;
    }
#pragma unroll
    for (int j = 0; j < 4; j++) {
        ulonglong2 t = rpB[j*8 + li];
        xb[2*j] = t.x; xb[2*j+1] = t.y;
    }

    unsigned long long s1a = xa[0], s2a = 0ull;
    unsigned long long s1b = xb[0], s2b = 0ull;
    ffma2(s2a, xa[0], xa[0]);
    ffma2(s2b, xb[0], xb[0]);
#pragma unroll
    for (int j = 1; j < 8; j++) {
        fadd2(s1a, xa[j]); ffma2(s2a, xa[j], xa[j]);
        fadd2(s1b, xb[j]); ffma2(s2b, xb[j], xb[j]);
    }
    float2 t;
    t = unpack2(s1a); float sa1 = t.x + t.y;
    t = unpack2(s2a); float sa2 = t.x + t.y;
    t = unpack2(s1b); float sb1 = t.x + t.y;
    t = unpack2(s2b); float sb2 = t.x + t.y;
#pragma unroll
    for (int off = 4; off; off >>= 1) {
        sa1 += __shfl_xor_sync(0xffffffffu, sa1, off);
        sa2 += __shfl_xor_sync(0xffffffffu, sa2, off);
        sb1 += __shfl_xor_sync(0xffffffffu, sb1, off);
        sb2 += __shfl_xor_sync(0xffffffffu, sb2, off);
    }
    float muA = sa1 * (1.f/128.f);
    float rsA = rsqrtf(fmaf(sa2, 1.f/128.f, -muA*muA) + 1e-5f);
    float muB = sb1 * (1.f/128.f);
    float rsB = rsqrtf(fmaf(sb2, 1.f/128.f, -muB*muB) + 1e-5f);

    const ulonglong2* wsp = (const ulonglong2*)swg;  // index: h*32 + j*8 + li
    float dhA = 0.f, dhB = 0.f;
#pragma unroll
    for (int p = 0; p < 4; p++) {
        unsigned long long aA0 = 0ull, aA1 = 0ull, aB0 = 0ull, aB1 = 0ull;
#pragma unroll
        for (int j = 0; j < 4; j++) {
            ulonglong2 w0 = wsp[(2*p  )*32 + j*8 + li];
            ulonglong2 w1 = wsp[(2*p+1)*32 + j*8 + li];
            ffma2(aA0, xa[2*j],   w0.x); ffma2(aA0, xa[2*j+1], w0.y);
            ffma2(aA1, xa[2*j],   w1.x); ffma2(aA1, xa[2*j+1], w1.y);
            ffma2(aB0, xb[2*j],   w0.x); ffma2(aB0, xb[2*j+1], w0.y);
            ffma2(aB1, xb[2*j],   w1.x); ffma2(aB1, xb[2*j+1], w1.y);
        }
        float2 u;
        u = unpack2(aA0); float fA0 = u.x + u.y;
        u = unpack2(aA1); float fA1 = u.x + u.y;
        u = unpack2(aB0); float fB0 = u.x + u.y;
        u = unpack2(aB1); float fB1 = u.x + u.y;
        float sA = b0 ? fA0 : fA1;
        float rA = (b0 ? fA1 : fA0) + __shfl_xor_sync(0xffffffffu, sA, 1);
        rA += __shfl_xor_sync(0xffffffffu, rA, 2);
        rA += __shfl_xor_sync(0xffffffffu, rA, 4);
        float sB = b0 ? fB0 : fB1;
        float rB = (b0 ? fB1 : fB0) + __shfl_xor_sync(0xffffffffu, sB, 1);
        rB += __shfl_xor_sync(0xffffffffu, rB, 2);
        rB += __shfl_xor_sync(0xffffffffu, rB, 4);
        if ((li >> 1) == p) { dhA = rA; dhB = rB; }
    }

    float valA = fmaf(rsA, dhA - muA*scw[li], sbb[li]);
    float valB = fmaf(rsB, dhB - muB*scw[li], sbb[li]);

    sval[warp*72 + li*9 + sub]     = valA;
    sval[warp*72 + li*9 + sub + 4] = valB;
    __syncthreads();

    unsigned rblk = pbid * 64u;
    unsigned bq = rblk >> 18;
    unsigned q  = (rblk >> 9) & 511u;
    unsigned k0 = rblk & 511u;
    int h  = tid >> 5;
    int kk = tid & 31;
    float* outp = g_pb + ((size_t)(bq*NH + h)*LSEQ + q)*LSEQ + k0;
    outp[kk]      = sval[(kk >> 3)*72      + h*9 + (kk & 7)];
    outp[kk + 32] = sval[((kk+32) >> 3)*72 + h*9 + (kk & 7)];
}

// ---------------- flash-style attention + gate (R4 config: 16 q rows, 512 blocks)
__global__ void __launch_bounds__(128) attn_kernel() {
    __shared__ __align__(16) float Qs[16*36];
    __shared__ __align__(16) float Ks[64*36];
    __shared__ __align__(16) float Vs[64*32];
    __shared__ __align__(16) float Ps[16*68];
    int tid = threadIdx.x;
    int bh = blockIdx.x >> 5;              // 512 blocks = 16 bh * 32 q-tiles
    int q0 = (blockIdx.x & 31) * 16;
    const float* Qg = g_q + (size_t)bh * LSEQ * HD;
    const float* Kg = g_k + (size_t)bh * LSEQ * HD;
    const float* Vg = g_v + (size_t)bh * LSEQ * HD;
    {
        int r = tid >> 3, c = tid & 7;
        *(float4*)&Qs[r*36 + c*4] = *(const float4*)(Qg + (size_t)(q0+r)*HD + c*4);
    }
    int ty = tid >> 3, tx = tid & 7;
    const float* pb = g_pb + ((size_t)bh * LSEQ + q0 + ty) * LSEQ;
    float m = __int_as_float(0xff800000u);
    float lsum = 0.f;
    float acc[4] = {0,0,0,0};

    for (int kt = 0; kt < LSEQ; kt += 64) {
        __syncthreads();
        for (int i = tid; i < 512; i += 128) {
            int r = i >> 3, c = i & 7;
            *(float4*)&Ks[r*36 + c*4] = *(const float4*)(Kg + (size_t)(kt+r)*HD + c*4);
        }
        for (int i = tid; i < 512; i += 128) {
            int r = i >> 3, c = i & 7;
            *(float4*)&Vs[r*32 + c*4] = *(const float4*)(Vg + (size_t)(kt+r)*HD + c*4);
        }
        __syncthreads();
        float sv[8];
#pragma unroll
        for (int j = 0; j < 8; j++) sv[j] = pb[kt + tx + 8*j];
#pragma unroll
        for (int d4 = 0; d4 < 8; d4++) {
            float4 a = *(float4*)&Qs[ty*36 + d4*4];
#pragma unroll
            for (int j = 0; j < 8; j++) {
                float4 kv = *(float4*)&Ks[(tx + 8*j)*36 + d4*4];
                sv[j] = fmaf(a.x,kv.x, fmaf(a.y,kv.y, fmaf(a.z,kv.z, fmaf(a.w,kv.w, sv[j]))));
            }
        }
        float mx = sv[0];
#pragma unroll
        for (int j = 1; j < 8; j++) mx = fmaxf(mx, sv[j]);
#pragma unroll
        for (int off = 4; off; off >>= 1)
            mx = fmaxf(mx, __shfl_xor_sync(0xffffffffu, mx, off));
        float mn = fmaxf(m, mx);
        float sc = __expf(m - mn);
        float sum = 0.f;
#pragma unroll
        for (int j = 0; j < 8; j++) { sv[j] = __expf(sv[j] - mn); sum += sv[j]; }
#pragma unroll
        for (int off = 4; off; off >>= 1)
            sum += __shfl_xor_sync(0xffffffffu, sum, off);
        lsum = lsum*sc + sum;
        m = mn;
#pragma unroll
        for (int j = 0; j < 4; j++) acc[j] *= sc;
#pragma unroll
        for (int j = 0; j < 8; j++) Ps[ty*68 + tx + 8*j] = sv[j];
        __syncthreads();
#pragma unroll
        for (int k4 = 0; k4 < 16; k4++) {
            float4 pa = *(float4*)&Ps[ty*68 + k4*4];
            float4 va = *(float4*)&Vs[(k4*4+0)*32 + tx*4];
            float4 vb = *(float4*)&Vs[(k4*4+1)*32 + tx*4];
            float4 vc = *(float4*)&Vs[(k4*4+2)*32 + tx*4];
            float4 vd = *(float4*)&Vs[(k4*4+3)*32 + tx*4];
            acc[0]=fmaf(pa.x,va.x,acc[0]); acc[1]=fmaf(pa.x,va.y,acc[1]); acc[2]=fmaf(pa.x,va.z,acc[2]); acc[3]=fmaf(pa.x,va.w,acc[3]);
            acc[0]=fmaf(pa.y,vb.x,acc[0]); acc[1]=fmaf(pa.y,vb.y,acc[1]); acc[2]=fmaf(pa.y,vb.z,acc[2]); acc[3]=fmaf(pa.y,vb.w,acc[3]);
            acc[0]=fmaf(pa.z,vc.x,acc[0]); acc[1]=fmaf(pa.z,vc.y,acc[1]); acc[2]=fmaf(pa.z,vc.z,acc[2]); acc[3]=fmaf(pa.z,vc.w,acc[3]);
            acc[0]=fmaf(pa.w,vd.x,acc[0]); acc[1]=fmaf(pa.w,vd.y,acc[1]); acc[2]=fmaf(pa.w,vd.z,acc[2]); acc[3]=fmaf(pa.w,vd.w,acc[3]);
        }
    }
    float inv = 1.f / lsum;
    int b = bh >> 3, h = bh & 7;
    int mrow = b * LSEQ + q0 + ty;
    float4 g = *(const float4*)(g_gate + (size_t)mrow * DG + h*HD + tx*4);
    float4 o = make_float4(acc[0]*inv*g.x, acc[1]*inv*g.y, acc[2]*inv*g.z, acc[3]*inv*g.w);
    *(float4*)(g_hid + (size_t)mrow*DG + h*HD + tx*4) = o;
}

// ---------------- final GEMM: hid @ Wout + bout ----------------
__global__ void __launch_bounds__(256) gemm_out(const float* __restrict__ Wout,
                                                const float* __restrict__ bout,
                                                float* __restrict__ out) {
    __shared__ __align__(16) float Ast[16*68];
    __shared__ __align__(16) float Bs [16*68];
    int tid = threadIdx.x;
    int bm = blockIdx.y * 64;
    int bn = blockIdx.x * 64;
    int ty = tid >> 4, tx = tid & 15;
    int ar = tid >> 2, ac4 = tid & 3;
    int br = tid >> 4, bc4 = tid & 15;
    float acc[4][4] = {};
    for (int kb = 0; kb < 256; kb += 16) {
        float4 av = *(const float4*)(g_hid + (size_t)(bm+ar)*256 + kb + ac4*4);
        Ast[(ac4*4+0)*68 + ar] = av.x;
        Ast[(ac4*4+1)*68 + ar] = av.y;
        Ast[(ac4*4+2)*68 + ar] = av.z;
        Ast[(ac4*4+3)*68 + ar] = av.w;
        *(float4*)&Bs[br*68 + bc4*4] = *(const float4*)(Wout + (size_t)(kb+br)*256 + bn + bc4*4);
        __syncthreads();
#pragma unroll
        for (int k = 0; k < 16; k++) {
            float4 a = *(float4*)&Ast[k*68 + ty*4];
            float4 b = *(float4*)&Bs [k*68 + tx*4];
            acc[0][0]=fmaf(a.x,b.x,acc[0][0]); acc[0][1]=fmaf(a.x,b.y,acc[0][1]);
            acc[0][2]=fmaf(a.x,b.z,acc[0][2]); acc[0][3]=fmaf(a.x,b.w,acc[0][3]);
            acc[1][0]=fmaf(a.y,b.x,acc[1][0]); acc[1][1]=fmaf(a.y,b.y,acc[1][1]);
            acc[1][2]=fmaf(a.y,b.z,acc[1][2]); acc[1][3]=fmaf(a.y,b.w,acc[1][3]);
            acc[2][0]=fmaf(a.z,b.x,acc[2][0]); acc[2][1]=fmaf(a.z,b.y,acc[2][1]);
            acc[2][2]=fmaf(a.z,b.z,acc[2][2]); acc[2][3]=fmaf(a.z,b.w,acc[2][3]);
            acc[3][0]=fmaf(a.w,b.x,acc[3][0]); acc[3][1]=fmaf(a.w,b.y,acc[3][1]);
            acc[3][2]=fmaf(a.w,b.z,acc[3][2]); acc[3][3]=fmaf(a.w,b.w,acc[3][3]);
        }
        __syncthreads();
    }
#pragma unroll
    for (int i = 0; i < 4; i++) {
#pragma unroll
        for (int j = 0; j < 4; j++) {
            int m = bm + ty*4 + i;
            int n = bn + tx*4 + j;
            out[(size_t)m*256 + n] = acc[i][j] + bout[n];
        }
    }
}

// ---------------- launch ----------------
extern "C" void kernel_launch(void* const* d_in, const int* in_sizes, int n_in,
                              void* d_out, int out_size) {
    const float* x       = (const float*)d_in[0];
    const float* bias    = (const float*)d_in[1];
    const float* g_gamma = (const float*)d_in[2];
    const float* g_beta  = (const float*)d_in[3];
    const float* b_gamma = (const float*)d_in[4];
    const float* b_beta  = (const float*)d_in[5];
    const float* Wq      = (const float*)d_in[6];
    const float* Wk      = (const float*)d_in[7];
    const float* Wv      = (const float*)d_in[8];
    const float* Wb      = (const float*)d_in[9];
    const float* Wg      = (const float*)d_in[10];
    const float* bg      = (const float*)d_in[11];
    const float* Wout    = (const float*)d_in[12];
    const float* bout    = (const float*)d_in[13];
    float* out = (float*)d_out;

    prep_and_lnx<<<129, 256>>>(b_gamma, b_beta, Wb, x, g_gamma, g_beta);
    fused_qkvg_pairln<<<8448, 256>>>(Wq, Wk, Wv, Wg, bg, bias);
    attn_kernel<<<512, 128>>>();
    gemm_out<<<dim3(4, 16), 256>>>(Wout, bout, out);
}

// round 10
// speedup vs baseline: 1.3860x; 1.0374x over previous
#include <cuda_runtime.h>
#include <math.h>

#define LSEQ 512
#define BATCH 2
#define DG 256
#define DB 128
#define NH 8
#define HD 32
#define BH (BATCH*NH)   // 16

// ---------------- scratch (device globals; no allocation allowed) ----------------
__device__ float g_xn[BATCH*LSEQ*DG];        // LN(x)                [1024][256]
__device__ float g_q[BH*LSEQ*HD];            // [b*h][l][32]
__device__ float g_k[BH*LSEQ*HD];            // pre-scaled by 1/sqrt(32)
__device__ float g_v[BH*LSEQ*HD];
__device__ float g_gate[BATCH*LSEQ*DG];      // sigmoid(xn@Wg+bg)    [1024][256]
__device__ float g_pb[(size_t)BH*LSEQ*LSEQ]; // pair bias            [b*h][q][k]
__device__ float g_hid[BATCH*LSEQ*DG];       // gate * attn_out      [1024][256]
__device__ float g_wgt[NH*DB];               // b_gamma[i]*Wb[i][h]  [h][i]
__device__ float g_cw[NH];                   // sum_i b_gamma[i]*Wb[i][h]
__device__ float g_bb[NH];                   // b_beta @ Wb[:,h]

// packed f32x2 helpers (sm_10x FFMA2 path — PTX only)
__device__ __forceinline__ void ffma2(unsigned long long& acc,
                                      unsigned long long a,
                                      unsigned long long b) {
    asm("fma.rn.f32x2 %0, %1, %2, %0;" : "+l"(acc) : "l"(a), "l"(b));
}
__device__ __forceinline__ void fadd2(unsigned long long& acc, unsigned long long a) {
    asm("add.rn.f32x2 %0, %1, %0;" : "+l"(acc) : "l"(a));
}
__device__ __forceinline__ float2 unpack2(unsigned long long v) {
    float2 r;
    asm("mov.b64 {%0, %1}, %2;" : "=f"(r.x), "=f"(r.y) : "l"(v));
    return r;
}

// ============ merged kernel 1: prep_wb (block 0) + ln_x (blocks 1..128) ============
__global__ void __launch_bounds__(256) prep_and_lnx(
        const float* __restrict__ b_gamma, const float* __restrict__ b_beta,
        const float* __restrict__ Wb,
        const float* __restrict__ x, const float* __restrict__ gamma,
        const float* __restrict__ beta) {
    int tid = threadIdx.x;
    if (blockIdx.x == 0) {
        // ---- prep_wb (128 threads) ----
        __shared__ float sc[NH][DB];
        __shared__ float sb[NH][DB];
        if (tid < DB) {
            float g = b_gamma[tid];
            float bt = b_beta[tid];
#pragma unroll
            for (int h = 0; h < NH; h++) {
                float w = Wb[tid*NH + h];
                g_wgt[h*DB + tid] = g * w;
                sc[h][tid] = g * w;
                sb[h][tid] = bt * w;
            }
        }
        __syncthreads();
        if (tid < NH) {
            float a = 0.f, b2 = 0.f;
            for (int j = 0; j < DB; j++) { a += sc[tid][j]; b2 += sb[tid][j]; }
            g_cw[tid] = a;
            g_bb[tid] = b2;
        }
        return;
    }
    // ---- ln_x: 8 warps -> 8 rows per block ----
    int warp = tid >> 5, lane = tid & 31;
    int row = (blockIdx.x - 1) * 8 + warp;     // 1024 rows over 128 blocks
    const float* rp = x + (size_t)row * DG;
    float4 v0 = *(const float4*)(rp + lane*4);
    float4 v1 = *(const float4*)(rp + 128 + lane*4);
    float s1 = v0.x+v0.y+v0.z+v0.w + v1.x+v1.y+v1.z+v1.w;
    float s2 = v0.x*v0.x+v0.y*v0.y+v0.z*v0.z+v0.w*v0.w
             + v1.x*v1.x+v1.y*v1.y+v1.z*v1.z+v1.w*v1.w;
#pragma unroll
    for (int off = 16; off; off >>= 1) {
        s1 += __shfl_xor_sync(0xffffffffu, s1, off);
        s2 += __shfl_xor_sync(0xffffffffu, s2, off);
    }
    float mu = s1 * (1.f/256.f);
    float var = s2 * (1.f/256.f) - mu*mu;
    float rstd = rsqrtf(var + 1e-5f);
    float4 gm0 = *(const float4*)(gamma + lane*4);
    float4 gm1 = *(const float4*)(gamma + 128 + lane*4);
    float4 bt0 = *(const float4*)(beta + lane*4);
    float4 bt1 = *(const float4*)(beta + 128 + lane*4);
    float4 o0, o1;
    o0.x = (v0.x-mu)*rstd*gm0.x + bt0.x; o0.y = (v0.y-mu)*rstd*gm0.y + bt0.y;
    o0.z = (v0.z-mu)*rstd*gm0.z + bt0.z; o0.w = (v0.w-mu)*rstd*gm0.w + bt0.w;
    o1.x = (v1.x-mu)*rstd*gm1.x + bt1.x; o1.y = (v1.y-mu)*rstd*gm1.y + bt1.y;
    o1.z = (v1.z-mu)*rstd*gm1.z + bt1.z; o1.w = (v1.w-mu)*rstd*gm1.w + bt1.w;
    *(float4*)(g_xn + (size_t)row*DG + lane*4) = o0;
    *(float4*)(g_xn + (size_t)row*DG + 128 + lane*4) = o1;
}

// ============ merged kernel 2: gemm_qkvg (blocks 0..255) + pair_ln (256..8447) ====
// gemm blocks first in grid order -> wave-1 schedules them alongside pair_ln
// blocks; the compute-bound gemm hides inside pair_ln's DRAM stalls.
__global__ void __launch_bounds__(256, 4) fused_qkvg_pairln(
        const float* __restrict__ Wq, const float* __restrict__ Wk,
        const float* __restrict__ Wv, const float* __restrict__ Wg,
        const float* __restrict__ bg, const float* __restrict__ bias) {
    __shared__ __align__(16) float smem[2*16*68];   // union for both branches
    int tid = threadIdx.x;

    if (blockIdx.x < 256) {
        // ---------------- gemm_qkvg ----------------
        float* Ast = smem;            // [k][m] transposed, padded 68
        float* Bs  = smem + 16*68;    // [k][n], padded 68
        int id = blockIdx.x;
        int bm = (id >> 4) * 64;
        int bn_g = (id & 15) * 64;           // 0..1023
        int which = bn_g >> 8;               // 0:Q 1:K 2:V 3:G
        int bn = bn_g & 255;
        const float* W = (which==0) ? Wq : (which==1) ? Wk : (which==2) ? Wv : Wg;
        int ty = tid >> 4, tx = tid & 15;
        int ar = tid >> 2, ac4 = tid & 3;
        int br = tid >> 4, bc4 = tid & 15;
        float acc[4][4] = {};
        for (int kb = 0; kb < 256; kb += 16) {
            float4 av = *(const float4*)(g_xn + (size_t)(bm+ar)*256 + kb + ac4*4);
            Ast[(ac4*4+0)*68 + ar] = av.x;
            Ast[(ac4*4+1)*68 + ar] = av.y;
            Ast[(ac4*4+2)*68 + ar] = av.z;
            Ast[(ac4*4+3)*68 + ar] = av.w;
            *(float4*)&Bs[br*68 + bc4*4] = *(const float4*)(W + (size_t)(kb+br)*256 + bn + bc4*4);
            __syncthreads();
#pragma unroll
            for (int k = 0; k < 16; k++) {
                float4 a = *(float4*)&Ast[k*68 + ty*4];
                float4 b = *(float4*)&Bs [k*68 + tx*4];
                acc[0][0]=fmaf(a.x,b.x,acc[0][0]); acc[0][1]=fmaf(a.x,b.y,acc[0][1]);
                acc[0][2]=fmaf(a.x,b.z,acc[0][2]); acc[0][3]=fmaf(a.x,b.w,acc[0][3]);
                acc[1][0]=fmaf(a.y,b.x,acc[1][0]); acc[1][1]=fmaf(a.y,b.y,acc[1][1]);
                acc[1][2]=fmaf(a.y,b.z,acc[1][2]); acc[1][3]=fmaf(a.y,b.w,acc[1][3]);
                acc[2][0]=fmaf(a.z,b.x,acc[2][0]); acc[2][1]=fmaf(a.z,b.y,acc[2][1]);
                acc[2][2]=fmaf(a.z,b.z,acc[2][2]); acc[2][3]=fmaf(a.z,b.w,acc[2][3]);
                acc[3][0]=fmaf(a.w,b.x,acc[3][0]); acc[3][1]=fmaf(a.w,b.y,acc[3][1]);
                acc[3][2]=fmaf(a.w,b.z,acc[3][2]); acc[3][3]=fmaf(a.w,b.w,acc[3][3]);
            }
            __syncthreads();
        }
        const float kscale = 0.17677669529663687f; // 1/sqrt(32)
#pragma unroll
        for (int i = 0; i < 4; i++) {
#pragma unroll
            for (int j = 0; j < 4; j++) {
                int m = bm + ty*4 + i;
                int n = bn + tx*4 + j;
                float v = acc[i][j];
                if (which < 3) {
                    if (which == 1) v *= kscale;
                    int b = m >> 9, pos = m & 511, h = n >> 5, d = n & 31;
                    float* dst = (which==0) ? g_q : (which==1) ? g_k : g_v;
                    dst[((size_t)(b*NH + h)*LSEQ + pos)*HD + d] = v;
                } else {
                    v = 1.f / (1.f + __expf(-(v + bg[n])));
                    g_gate[(size_t)m*DG + n] = v;
                }
            }
        }
        return;
    }

    // ---------------- pair_ln ----------------
    // Warp = 8 rows (sub -> rows base+sub, base+sub+4), lane li owns contiguous
    // 16B chunks. Eager head-pair reduction keeps regs <= 64.
    float* swg = smem;                        // NH*DB = 1024 floats
    float* scw = smem + NH*DB;                // 8
    float* sbb = smem + NH*DB + NH;           // 8
    float* sval = smem + NH*DB + 2*NH;        // 8*72 = 576
    unsigned pbid = blockIdx.x - 256u;
    for (int i = tid; i < NH*DB; i += 256) swg[i] = g_wgt[i];
    if (tid < NH) { scw[tid] = g_cw[tid]; sbb[tid] = g_bb[tid]; }
    __syncthreads();
    int warp = tid >> 5, lane = tid & 31;
    int sub = lane >> 3, li = lane & 7;
    int b0 = li & 1;
    unsigned rowA = pbid * 64u + warp * 8u + sub;   // < 524288
    const ulonglong2* rpA = (const ulonglong2*)(bias + (size_t)rowA * DB);
    const ulonglong2* rpB = (const ulonglong2*)(bias + (size_t)(rowA + 4u) * DB);

    unsigned long long xa[8], xb[8];
#pragma unroll
    for (int j = 0; j < 4; j++) {
        ulonglong2 t = rpA[j*8 + li];
        xa[2*j] = t.x; xa[2*j+1] = t.y;
    }
#pragma unroll
    for (int j = 0; j < 4; j++) {
        ulonglong2 t = rpB[j*8 + li];
        xb[2*j] = t.x; xb[2*j+1] = t.y;
    }

    unsigned long long s1a = xa[0], s2a = 0ull;
    unsigned long long s1b = xb[0], s2b = 0ull;
    ffma2(s2a, xa[0], xa[0]);
    ffma2(s2b, xb[0], xb[0]);
#pragma unroll
    for (int j = 1; j < 8; j++) {
        fadd2(s1a, xa[j]); ffma2(s2a, xa[j], xa[j]);
        fadd2(s1b, xb[j]); ffma2(s2b, xb[j], xb[j]);
    }
    float2 t;
    t = unpack2(s1a); float sa1 = t.x + t.y;
    t = unpack2(s2a); float sa2 = t.x + t.y;
    t = unpack2(s1b); float sb1 = t.x + t.y;
    t = unpack2(s2b); float sb2 = t.x + t.y;
#pragma unroll
    for (int off = 4; off; off >>= 1) {
        sa1 += __shfl_xor_sync(0xffffffffu, sa1, off);
        sa2 += __shfl_xor_sync(0xffffffffu, sa2, off);
        sb1 += __shfl_xor_sync(0xffffffffu, sb1, off);
        sb2 += __shfl_xor_sync(0xffffffffu, sb2, off);
    }
    float muA = sa1 * (1.f/128.f);
    float rsA = rsqrtf(fmaf(sa2, 1.f/128.f, -muA*muA) + 1e-5f);
    float muB = sb1 * (1.f/128.f);
    float rsB = rsqrtf(fmaf(sb2, 1.f/128.f, -muB*muB) + 1e-5f);

    const ulonglong2* wsp = (const ulonglong2*)swg;  // index: h*32 + j*8 + li
    float dhA = 0.f, dhB = 0.f;
#pragma unroll
    for (int p = 0; p < 4; p++) {
        unsigned long long aA0 = 0ull, aA1 = 0ull, aB0 = 0ull, aB1 = 0ull;
#pragma unroll
        for (int j = 0; j < 4; j++) {
            ulonglong2 w0 = wsp[(2*p  )*32 + j*8 + li];
            ulonglong2 w1 = wsp[(2*p+1)*32 + j*8 + li];
            ffma2(aA0, xa[2*j],   w0.x); ffma2(aA0, xa[2*j+1], w0.y);
            ffma2(aA1, xa[2*j],   w1.x); ffma2(aA1, xa[2*j+1], w1.y);
            ffma2(aB0, xb[2*j],   w0.x); ffma2(aB0, xb[2*j+1], w0.y);
            ffma2(aB1, xb[2*j],   w1.x); ffma2(aB1, xb[2*j+1], w1.y);
        }
        float2 u;
        u = unpack2(aA0); float fA0 = u.x + u.y;
        u = unpack2(aA1); float fA1 = u.x + u.y;
        u = unpack2(aB0); float fB0 = u.x + u.y;
        u = unpack2(aB1); float fB1 = u.x + u.y;
        float sA = b0 ? fA0 : fA1;
        float rA = (b0 ? fA1 : fA0) + __shfl_xor_sync(0xffffffffu, sA, 1);
        rA += __shfl_xor_sync(0xffffffffu, rA, 2);
        rA += __shfl_xor_sync(0xffffffffu, rA, 4);
        float sB = b0 ? fB0 : fB1;
        float rB = (b0 ? fB1 : fB0) + __shfl_xor_sync(0xffffffffu, sB, 1);
        rB += __shfl_xor_sync(0xffffffffu, rB, 2);
        rB += __shfl_xor_sync(0xffffffffu, rB, 4);
        if ((li >> 1) == p) { dhA = rA; dhB = rB; }
    }

    float valA = fmaf(rsA, dhA - muA*scw[li], sbb[li]);
    float valB = fmaf(rsB, dhB - muB*scw[li], sbb[li]);

    sval[warp*72 + li*9 + sub]     = valA;
    sval[warp*72 + li*9 + sub + 4] = valB;
    __syncthreads();

    unsigned rblk = pbid * 64u;
    unsigned bq = rblk >> 18;
    unsigned q  = (rblk >> 9) & 511u;
    unsigned k0 = rblk & 511u;
    int h  = tid >> 5;
    int kk = tid & 31;
    float* outp = g_pb + ((size_t)(bq*NH + h)*LSEQ + q)*LSEQ + k0;
    outp[kk]      = sval[(kk >> 3)*72      + h*9 + (kk & 7)];
    outp[kk + 32] = sval[((kk+32) >> 3)*72 + h*9 + (kk & 7)];
}

// ---------------- flash-style attention + gate (R4 config: 16 q rows, 512 blocks)
__global__ void __launch_bounds__(128) attn_kernel() {
    __shared__ __align__(16) float Qs[16*36];
    __shared__ __align__(16) float Ks[64*36];
    __shared__ __align__(16) float Vs[64*32];
    __shared__ __align__(16) float Ps[16*68];
    int tid = threadIdx.x;
    int bh = blockIdx.x >> 5;              // 512 blocks = 16 bh * 32 q-tiles
    int q0 = (blockIdx.x & 31) * 16;
    const float* Qg = g_q + (size_t)bh * LSEQ * HD;
    const float* Kg = g_k + (size_t)bh * LSEQ * HD;
    const float* Vg = g_v + (size_t)bh * LSEQ * HD;
    {
        int r = tid >> 3, c = tid & 7;
        *(float4*)&Qs[r*36 + c*4] = *(const float4*)(Qg + (size_t)(q0+r)*HD + c*4);
    }
    int ty = tid >> 3, tx = tid & 7;
    const float* pb = g_pb + ((size_t)bh * LSEQ + q0 + ty) * LSEQ;
    float m = __int_as_float(0xff800000u);
    float lsum = 0.f;
    float acc[4] = {0,0,0,0};

    for (int kt = 0; kt < LSEQ; kt += 64) {
        __syncthreads();
        for (int i = tid; i < 512; i += 128) {
            int r = i >> 3, c = i & 7;
            *(float4*)&Ks[r*36 + c*4] = *(const float4*)(Kg + (size_t)(kt+r)*HD + c*4);
        }
        for (int i = tid; i < 512; i += 128) {
            int r = i >> 3, c = i & 7;
            *(float4*)&Vs[r*32 + c*4] = *(const float4*)(Vg + (size_t)(kt+r)*HD + c*4);
        }
        __syncthreads();
        float sv[8];
#pragma unroll
        for (int j = 0; j < 8; j++) sv[j] = pb[kt + tx + 8*j];
#pragma unroll
        for (int d4 = 0; d4 < 8; d4++) {
            float4 a = *(float4*)&Qs[ty*36 + d4*4];
#pragma unroll
            for (int j = 0; j < 8; j++) {
                float4 kv = *(float4*)&Ks[(tx + 8*j)*36 + d4*4];
                sv[j] = fmaf(a.x,kv.x, fmaf(a.y,kv.y, fmaf(a.z,kv.z, fmaf(a.w,kv.w, sv[j]))));
            }
        }
        float mx = sv[0];
#pragma unroll
        for (int j = 1; j < 8; j++) mx = fmaxf(mx, sv[j]);
#pragma unroll
        for (int off = 4; off; off >>= 1)
            mx = fmaxf(mx, __shfl_xor_sync(0xffffffffu, mx, off));
        float mn = fmaxf(m, mx);
        float sc = __expf(m - mn);
        float sum = 0.f;
#pragma unroll
        for (int j = 0; j < 8; j++) { sv[j] = __expf(sv[j] - mn); sum += sv[j]; }
#pragma unroll
        for (int off = 4; off; off >>= 1)
            sum += __shfl_xor_sync(0xffffffffu, sum, off);
        lsum = lsum*sc + sum;
        m = mn;
#pragma unroll
        for (int j = 0; j < 4; j++) acc[j] *= sc;
#pragma unroll
        for (int j = 0; j < 8; j++) Ps[ty*68 + tx + 8*j] = sv[j];
        __syncthreads();
#pragma unroll
        for (int k4 = 0; k4 < 16; k4++) {
            float4 pa = *(float4*)&Ps[ty*68 + k4*4];
            float4 va = *(float4*)&Vs[(k4*4+0)*32 + tx*4];
            float4 vb = *(float4*)&Vs[(k4*4+1)*32 + tx*4];
            float4 vc = *(float4*)&Vs[(k4*4+2)*32 + tx*4];
            float4 vd = *(float4*)&Vs[(k4*4+3)*32 + tx*4];
            acc[0]=fmaf(pa.x,va.x,acc[0]); acc[1]=fmaf(pa.x,va.y,acc[1]); acc[2]=fmaf(pa.x,va.z,acc[2]); acc[3]=fmaf(pa.x,va.w,acc[3]);
            acc[0]=fmaf(pa.y,vb.x,acc[0]); acc[1]=fmaf(pa.y,vb.y,acc[1]); acc[2]=fmaf(pa.y,vb.z,acc[2]); acc[3]=fmaf(pa.y,vb.w,acc[3]);
            acc[0]=fmaf(pa.z,vc.x,acc[0]); acc[1]=fmaf(pa.z,vc.y,acc[1]); acc[2]=fmaf(pa.z,vc.z,acc[2]); acc[3]=fmaf(pa.z,vc.w,acc[3]);
            acc[0]=fmaf(pa.w,vd.x,acc[0]); acc[1]=fmaf(pa.w,vd.y,acc[1]); acc[2]=fmaf(pa.w,vd.z,acc[2]); acc[3]=fmaf(pa.w,vd.w,acc[3]);
        }
    }
    float inv = 1.f / lsum;
    int b = bh >> 3, h = bh & 7;
    int mrow = b * LSEQ + q0 + ty;
    float4 g = *(const float4*)(g_gate + (size_t)mrow * DG + h*HD + tx*4);
    float4 o = make_float4(acc[0]*inv*g.x, acc[1]*inv*g.y, acc[2]*inv*g.z, acc[3]*inv*g.w);
    *(float4*)(g_hid + (size_t)mrow*DG + h*HD + tx*4) = o;
}

// ---------------- final GEMM: hid @ Wout + bout ----------------
// Re-tiled 32M x 64N -> 128 blocks (~1/SM): fixes the 64-block grid starvation
// (occ was 12.9%, 22.4us for 134 MFLOP). A-tile pad = 34 so the 4-way
// transpose-store hits distinct banks (offset per ac4 = 8 banks) and float2
// row reads stay 8B-aligned (136 = 17*8).
__global__ void __launch_bounds__(256) gemm_out(const float* __restrict__ Wout,
                                                const float* __restrict__ bout,
                                                float* __restrict__ out) {
    __shared__ __align__(16) float Ast[16*34];   // [k][m] transposed, pad 34
    __shared__ __align__(16) float Bs [16*68];   // [k][n], pad 68
    int tid = threadIdx.x;
    int bm = blockIdx.y * 32;
    int bn = blockIdx.x * 64;
    int ty = tid >> 4, tx = tid & 15;            // rows 2ty,2ty+1 ; cols tx*4
    int ar = tid >> 2, ac4 = tid & 3;            // threads 0..127 load A
    int br = tid >> 4, bc4 = tid & 15;
    float acc[2][4] = {};
    for (int kb = 0; kb < 256; kb += 16) {
        if (tid < 128) {
            float4 av = *(const float4*)(g_hid + (size_t)(bm+ar)*256 + kb + ac4*4);
            Ast[(ac4*4+0)*34 + ar] = av.x;
            Ast[(ac4*4+1)*34 + ar] = av.y;
            Ast[(ac4*4+2)*34 + ar] = av.z;
            Ast[(ac4*4+3)*34 + ar] = av.w;
        }
        *(float4*)&Bs[br*68 + bc4*4] = *(const float4*)(Wout + (size_t)(kb+br)*256 + bn + bc4*4);
        __syncthreads();
#pragma unroll
        for (int k = 0; k < 16; k++) {
            float2 a = *(float2*)&Ast[k*34 + ty*2];
            float4 b = *(float4*)&Bs [k*68 + tx*4];
            acc[0][0]=fmaf(a.x,b.x,acc[0][0]); acc[0][1]=fmaf(a.x,b.y,acc[0][1]);
            acc[0][2]=fmaf(a.x,b.z,acc[0][2]); acc[0][3]=fmaf(a.x,b.w,acc[0][3]);
            acc[1][0]=fmaf(a.y,b.x,acc[1][0]); acc[1][1]=fmaf(a.y,b.y,acc[1][1]);
            acc[1][2]=fmaf(a.y,b.z,acc[1][2]); acc[1][3]=fmaf(a.y,b.w,acc[1][3]);
        }
        __syncthreads();
    }
    float4 bo = *(const float4*)(bout + bn + tx*4);
#pragma unroll
    for (int i = 0; i < 2; i++) {
        int m = bm + ty*2 + i;
        float4 o = make_float4(acc[i][0] + bo.x, acc[i][1] + bo.y,
                               acc[i][2] + bo.z, acc[i][3] + bo.w);
        *(float4*)(out + (size_t)m*256 + bn + tx*4) = o;
    }
}

// ---------------- launch ----------------
extern "C" void kernel_launch(void* const* d_in, const int* in_sizes, int n_in,
                              void* d_out, int out_size) {
    const float* x       = (const float*)d_in[0];
    const float* bias    = (const float*)d_in[1];
    const float* g_gamma = (const float*)d_in[2];
    const float* g_beta  = (const float*)d_in[3];
    const float* b_gamma = (const float*)d_in[4];
    const float* b_beta  = (const float*)d_in[5];
    const float* Wq      = (const float*)d_in[6];
    const float* Wk      = (const float*)d_in[7];
    const float* Wv      = (const float*)d_in[8];
    const float* Wb      = (const float*)d_in[9];
    const float* Wg      = (const float*)d_in[10];
    const float* bg      = (const float*)d_in[11];
    const float* Wout    = (const float*)d_in[12];
    const float* bout    = (const float*)d_in[13];
    float* out = (float*)d_out;

    prep_and_lnx<<<129, 256>>>(b_gamma, b_beta, Wb, x, g_gamma, g_beta);
    fused_qkvg_pairln<<<8448, 256>>>(Wq, Wk, Wv, Wg, bg, bias);
    attn_kernel<<<512, 128>>>();
    gemm_out<<<dim3(4, 32), 256>>>(Wout, bout, out);
}